// round 9
// baseline (speedup 1.0000x reference)
#include <cuda_runtime.h>
#include <cuda_bf16.h>
#include <cuda_fp16.h>
#include <cstdint>
#include <math.h>

#define N_HEADS 16
#define HIDDEN  1024
#define HS      64
#define BATCH   2
#define SEQ     2048
#define M_ROWS  (BATCH * SEQ)      // 4096
#define N_COLS  (3 * HIDDEN)       // 3072

// Scratch QKV, flat [u=2s+b][h][...]:
//   Q (u=0,1) and K (u=2,3): [t][d] row-major
//   V (u=4,5):               [d][t] row-major  (V^T, for bf16 mma B operand)
__device__ float g_qkv[(size_t)6 * N_HEADS * SEQ * HS];

// ---------------------------------------------------------------------------
// Helpers
// ---------------------------------------------------------------------------
__device__ __forceinline__ uint32_t smem_u32(const void* p) {
    uint32_t a;
    asm("{ .reg .u64 t; cvta.to.shared.u64 t, %1; cvt.u32.u64 %0, t; }"
        : "=r"(a) : "l"(p));
    return a;
}
__device__ __forceinline__ void mma_fp16(float* d, const uint32_t* a,
                                         const uint32_t* b) {
    asm volatile(
        "mma.sync.aligned.m16n8k16.row.col.f32.f16.f16.f32 "
        "{%0,%1,%2,%3}, {%4,%5,%6,%7}, {%8,%9}, {%0,%1,%2,%3};"
        : "+f"(d[0]), "+f"(d[1]), "+f"(d[2]), "+f"(d[3])
        : "r"(a[0]), "r"(a[1]), "r"(a[2]), "r"(a[3]),
          "r"(b[0]), "r"(b[1]));
}
__device__ __forceinline__ void mma_bf16(float* d, const uint32_t* a,
                                         const uint32_t* b) {
    asm volatile(
        "mma.sync.aligned.m16n8k16.row.col.f32.bf16.bf16.f32 "
        "{%0,%1,%2,%3}, {%4,%5,%6,%7}, {%8,%9}, {%0,%1,%2,%3};"
        : "+f"(d[0]), "+f"(d[1]), "+f"(d[2]), "+f"(d[3])
        : "r"(a[0]), "r"(a[1]), "r"(a[2]), "r"(a[3]),
          "r"(b[0]), "r"(b[1]));
}
__device__ __forceinline__ uint32_t pack_h2(float x, float y) {
    __half2 h = __floats2half2_rn(x, y);
    return *reinterpret_cast<uint32_t*>(&h);
}
// Split (x,y) into bf16x2 hi and bf16x2 lo (residual). Low half = x (= lower k).
__device__ __forceinline__ void split_bf2(float x, float y,
                                          uint32_t& hi, uint32_t& lo) {
    __nv_bfloat16 hx = __float2bfloat16_rn(x);
    __nv_bfloat16 hy = __float2bfloat16_rn(y);
    __nv_bfloat162 hp; hp.x = hx; hp.y = hy;
    hi = *reinterpret_cast<uint32_t*>(&hp);
    __nv_bfloat162 lp;
    lp.x = __float2bfloat16_rn(x - __bfloat162float(hx));
    lp.y = __float2bfloat16_rn(y - __bfloat162float(hy));
    lo = *reinterpret_cast<uint32_t*>(&lp);
}
__device__ __forceinline__ void cp16(uint32_t dst, const void* src) {
    asm volatile("cp.async.cg.shared.global [%0], [%1], 16;"
                 :: "r"(dst), "l"(src) : "memory");
}
#define CP_COMMIT() asm volatile("cp.async.commit_group;" ::: "memory")
#define CP_WAIT1()  asm volatile("cp.async.wait_group 1;" ::: "memory")
#define CP_WAIT0()  asm volatile("cp.async.wait_group 0;" ::: "memory")

// ---------------------------------------------------------------------------
// Kernel 1: QKV GEMM via mma.sync fp16 m16n8k16 (fp32 staging via cp.async,
// fp16 has the same 10-bit mantissa as tf32 -> same error, half the mma slots).
// Epilogue: bias + reshape scatter (g = 3r + c/1024; e = c%1024;
// u=g>>11; t=g&2047; h=e&15; d=e>>4); V third written d-major ([d][t]).
// ---------------------------------------------------------------------------
#define GBK   32
#define GNIT  (HIDDEN / GBK)          // 32
#define CSTR  132
#define GEMM_SMEM_BYTES (CSTR * 128 * 4)

// Element accessors for the swizzled fp32 tiles
__device__ __forceinline__ float2 lda2(const float* Ab, int r, int k) {
    uint32_t off = (uint32_t)r * 32 + ((((uint32_t)k) & ~3u) ^ (((uint32_t)(r & 7)) << 2))
                 + ((uint32_t)k & 3u);
    return *(const float2*)(Ab + off);
}
__device__ __forceinline__ float ldb1(const float* Bb, int kk, int n) {
    uint32_t off = (uint32_t)kk * 128 + ((((uint32_t)n) & ~3u) ^ (((uint32_t)(kk & 3)) << 3))
                 + ((uint32_t)n & 3u);
    return Bb[off];
}

__global__ void __launch_bounds__(256, 2) qkv_gemm_tc(
    const float* __restrict__ x, const float* __restrict__ W,
    const float* __restrict__ bias)
{
    extern __shared__ float smf[];
    const uint32_t sbase = smem_u32(smf);
    const int tid  = threadIdx.x;
    const int lane = tid & 31;
    const int wid  = tid >> 5;
    const int wm   = wid & 1;
    const int wn   = wid >> 1;
    const int m0 = blockIdx.y * 128, n0 = blockIdx.x * 128;

    const int a_row = tid >> 3;
    const int a_k4  = (tid & 7) << 2;
    const int b_krw = tid >> 5;
    const int b_n4  = (tid & 31) << 2;
    const float* Ag = x + (size_t)(m0 + a_row) * HIDDEN + a_k4;
    const float* Bg = W + (size_t)b_krw * N_COLS + n0 + b_n4;
    const uint32_t a_st = a_row * 32 + (a_k4 ^ (((uint32_t)(a_row & 7)) << 2));
    const uint32_t b_st = b_krw * 128 + (b_n4 ^ (((uint32_t)(b_krw & 3)) << 3));

    const int lr = lane >> 2, lc = lane & 3;

    float acc[4][4][4] = {};

    #pragma unroll
    for (int i = 0; i < 4; i++) {
        cp16(sbase + (a_st + i * 1024) * 4, Ag + (size_t)i * 32 * HIDDEN);
        cp16(sbase + (8192 + b_st + i * 1024) * 4, Bg + (size_t)i * 8 * N_COLS);
    }
    CP_COMMIT();

    for (int it = 0; it < GNIT; ++it) {
        const uint32_t buf = it & 1;
        if (it + 1 < GNIT) {
            const uint32_t nb = buf ^ 1;
            const float* Agn = Ag + (it + 1) * GBK;
            const float* Bgn = Bg + (size_t)(it + 1) * GBK * N_COLS;
            #pragma unroll
            for (int i = 0; i < 4; i++) {
                cp16(sbase + (nb * 4096 + a_st + i * 1024) * 4,
                     Agn + (size_t)i * 32 * HIDDEN);
                cp16(sbase + (8192 + nb * 4096 + b_st + i * 1024) * 4,
                     Bgn + (size_t)i * 8 * N_COLS);
            }
            CP_COMMIT();
            CP_WAIT1();
        } else {
            CP_WAIT0();
        }
        __syncthreads();

        const float* Ab = smf + buf * 4096;
        const float* Bb = smf + 8192 + buf * 4096;
        #pragma unroll
        for (int ks = 0; ks < 2; ks++) {          // two k16 steps per k32 tile
            const int kb = ks * 16;
            const int k1 = kb + 2 * lc;           // A k-pair 1
            const int k2 = k1 + 8;                // A k-pair 2
            uint32_t af[4][4], bf[4][2];
            #pragma unroll
            for (int mf = 0; mf < 4; mf++) {
                const int r = wm * 64 + mf * 16 + lr;
                float2 p0 = lda2(Ab, r, k1);
                float2 p1 = lda2(Ab, r + 8, k1);
                float2 p2 = lda2(Ab, r, k2);
                float2 p3 = lda2(Ab, r + 8, k2);
                af[mf][0] = pack_h2(p0.x, p0.y);
                af[mf][1] = pack_h2(p1.x, p1.y);
                af[mf][2] = pack_h2(p2.x, p2.y);
                af[mf][3] = pack_h2(p3.x, p3.y);
            }
            #pragma unroll
            for (int nf = 0; nf < 4; nf++) {
                const int n = wn * 32 + nf * 8 + lr;
                bf[nf][0] = pack_h2(ldb1(Bb, k1, n), ldb1(Bb, k1 + 1, n));
                bf[nf][1] = pack_h2(ldb1(Bb, k2, n), ldb1(Bb, k2 + 1, n));
            }
            #pragma unroll
            for (int mf = 0; mf < 4; mf++)
                #pragma unroll
                for (int nf = 0; nf < 4; nf++)
                    mma_fp16(acc[mf][nf], af[mf], bf[nf]);
        }
        __syncthreads();
    }

    // ---- Epilogue via smem ----
    float* Cs = smf;
    #pragma unroll
    for (int mf = 0; mf < 4; mf++) {
        const int r = wm * 64 + mf * 16 + lr;
        #pragma unroll
        for (int nf = 0; nf < 4; nf++) {
            const int c = wn * 32 + nf * 8 + 2 * lc;
            *(float2*)&Cs[r * CSTR + c]       = make_float2(acc[mf][nf][0], acc[mf][nf][1]);
            *(float2*)&Cs[(r + 8) * CSTR + c] = make_float2(acc[mf][nf][2], acc[mf][nf][3]);
        }
    }
    __syncthreads();

    {
        const int rr = tid >> 1;
        const int half = tid & 1;
        const int r = m0 + rr;
        const int g = 3 * r + (n0 >> 10);
        const int u = g >> 11, t = g & 2047;
        const int d0 = (n0 & 1023) >> 4;
        const bool isV = ((u >> 1) == 2);
        #pragma unroll
        for (int j = 0; j < 8; j++) {
            const int hh = half * 8 + j;
            float o[8];
            #pragma unroll
            for (int e = 0; e < 8; e++)
                o[e] = Cs[rr * CSTR + hh + 16 * e] + __ldg(&bias[n0 + hh + 16 * e]);
            float* base = g_qkv + (size_t)(u * 16 + hh) * (SEQ * HS);
            if (isV) {
                // V stored d-major: [d][t]
                #pragma unroll
                for (int e = 0; e < 8; e++)
                    base[(size_t)(d0 + e) * SEQ + t] = o[e];
            } else {
                float* dst = base + (size_t)t * HS + d0;
                *(float4*)dst       = make_float4(o[0], o[1], o[2], o[3]);
                *(float4*)(dst + 4) = make_float4(o[4], o[5], o[6], o[7]);
            }
        }
    }
}

// ---------------------------------------------------------------------------
// Kernel 2: flash attention via mma.sync bf16 m16n8k16, split-2 precision.
// (unchanged from R8 — measured 222us, rel_err contribution negligible)
// ---------------------------------------------------------------------------
#define ATT_SMEM_BYTES (16384 * 4)

__global__ void __launch_bounds__(256, 2) attn_mma(float* __restrict__ out) {
    extern __shared__ uint32_t sm[];
    uint32_t* Qhi = sm;                 // 4096
    uint32_t* Qlo = sm + 4096;          // 4096
    uint32_t* Khi = sm + 8192;          // 2048
    uint32_t* Klo = sm + 10240;         // 2048
    uint32_t* Vhi = sm + 12288;         // 2048
    uint32_t* Vlo = sm + 14336;         // 2048

    const int tid  = threadIdx.x;
    const int lane = tid & 31;
    const int w    = tid >> 5;          // warp 0..7, rows [16w,16w+16)
    const int lr   = lane >> 2, lc = lane & 3;
    const int qtile = (int)(gridDim.x - 1) - (int)blockIdx.x;  // long CTAs first
    const int h = blockIdx.y, b = blockIdx.z;
    const int q0 = qtile * 128;

    const float* qg  = g_qkv + (size_t)(b * 16 + h) * (SEQ * HS);        // [t][d]
    const float* kg  = g_qkv + (size_t)((2 + b) * 16 + h) * (SEQ * HS);  // [t][d]
    const float* vtg = g_qkv + (size_t)((4 + b) * 16 + h) * (SEQ * HS);  // [d][t]

    // ---- Load Q tile (scaled by 2^-3, exact), split-2 into bf16x2 pairs ----
    #pragma unroll
    for (int i = 0; i < 8; i++) {
        int f = tid + i * 256;
        int r = f >> 4, d4 = (f & 15) << 2;
        float4 v = *(const float4*)(qg + (size_t)(q0 + r) * HS + d4);
        v.x *= 0.125f; v.y *= 0.125f; v.z *= 0.125f; v.w *= 0.125f;
        uint32_t idx = r * 32 + (((uint32_t)d4 >> 1) ^ (((uint32_t)(r & 7)) << 2));
        uint2 hi, lo;
        split_bf2(v.x, v.y, hi.x, lo.x);
        split_bf2(v.z, v.w, hi.y, lo.y);
        *(uint2*)&Qhi[idx] = hi;
        *(uint2*)&Qlo[idx] = lo;
    }

    float oacc[8][4];
    #pragma unroll
    for (int j = 0; j < 8; j++)
        #pragma unroll
        for (int k = 0; k < 4; k++) oacc[j][k] = 0.0f;
    float m0 = -1e30f, m1 = -1e30f, l0 = 0.0f, l1 = 0.0f;

    const int st_r  = tid >> 4;               // 0..15 (+16i)
    const int st_c4 = (tid & 15) << 2;        // 0..60
    const uint32_t xmask = (uint32_t)(lane >> 2 & 7) << 2;  // = lr<<2

    const int nkt = 2 * qtile + 2;
    for (int kt = 0; kt < nkt; kt++) {
        const int k0g = kt * 64;

        // ---- K quad: LDG issued pre-sync ----
        float4 kreg[4];
        uint32_t kidx[4];
        #pragma unroll
        for (int i = 0; i < 4; i++) {
            int rr = st_r + i * 16;
            kreg[i] = *(const float4*)(kg + (size_t)(k0g + rr) * HS + st_c4);
            kidx[i] = rr * 32 + (((uint32_t)st_c4 >> 1) ^ (((uint32_t)(rr & 7)) << 2));
        }
        __syncthreads();   // prev-tile consumers done
        #pragma unroll
        for (int i = 0; i < 4; i++) {
            uint2 hi, lo;
            split_bf2(kreg[i].x, kreg[i].y, hi.x, lo.x);
            split_bf2(kreg[i].z, kreg[i].w, hi.y, lo.y);
            *(uint2*)&Khi[kidx[i]] = hi;
            *(uint2*)&Klo[kidx[i]] = lo;
        }
        // ---- V^T quad ----
        float4 vreg[4];
        #pragma unroll
        for (int i = 0; i < 4; i++)
            vreg[i] = *(const float4*)(vtg + (size_t)(st_r + i * 16) * SEQ + k0g + st_c4);
        #pragma unroll
        for (int i = 0; i < 4; i++) {
            uint2 hi, lo;
            split_bf2(vreg[i].x, vreg[i].y, hi.x, lo.x);
            split_bf2(vreg[i].z, vreg[i].w, hi.y, lo.y);
            *(uint2*)&Vhi[kidx[i]] = hi;
            *(uint2*)&Vlo[kidx[i]] = lo;
        }
        __syncthreads();   // tiles visible

        // Full-skip: all cols of this tile above all rows of this warp
        if (k0g > q0 + 16 * w + 15) continue;

        // ---- S = Q K^T (bf16 split-2, 3-term) ----
        float sacc[8][4];
        #pragma unroll
        for (int j = 0; j < 8; j++)
            #pragma unroll
            for (int k = 0; k < 4; k++) sacc[j][k] = 0.0f;

        const int r = 16 * w + lr;
        const uint32_t qbase = r * 32;
        #pragma unroll
        for (int ks = 0; ks < 4; ks++) {
            const uint32_t c1x = ((uint32_t)(8 * ks + lc)) ^ xmask;
            const uint32_t c2x = ((uint32_t)(8 * ks + lc + 4)) ^ xmask;
            uint32_t ahi[4], alo[4];
            ahi[0] = Qhi[qbase + c1x];       alo[0] = Qlo[qbase + c1x];
            ahi[1] = Qhi[qbase + 256 + c1x]; alo[1] = Qlo[qbase + 256 + c1x];
            ahi[2] = Qhi[qbase + c2x];       alo[2] = Qlo[qbase + c2x];
            ahi[3] = Qhi[qbase + 256 + c2x]; alo[3] = Qlo[qbase + 256 + c2x];
            #pragma unroll
            for (int j = 0; j < 8; j++) {
                const uint32_t nb = (uint32_t)(8 * j + lr) * 32;
                uint32_t bh[2] = { Khi[nb + c1x], Khi[nb + c2x] };
                mma_bf16(sacc[j], ahi, bh);
                mma_bf16(sacc[j], alo, bh);
                uint32_t bl[2] = { Klo[nb + c1x], Klo[nb + c2x] };
                mma_bf16(sacc[j], ahi, bl);
            }
        }

        // ---- Causal mask (only near diagonal) ----
        const int row0 = q0 + 16 * w + lr;
        if (k0g + 63 > q0 + 16 * w) {
            #pragma unroll
            for (int j = 0; j < 8; j++) {
                const int c0 = k0g + 8 * j + 2 * lc;
                if (c0 > row0)         sacc[j][0] = -1e30f;
                if (c0 + 1 > row0)     sacc[j][1] = -1e30f;
                if (c0 > row0 + 8)     sacc[j][2] = -1e30f;
                if (c0 + 1 > row0 + 8) sacc[j][3] = -1e30f;
            }
        }

        // ---- Online softmax (registers + quad shuffles) ----
        float ml0 = -1e30f, ml1 = -1e30f;
        #pragma unroll
        for (int j = 0; j < 8; j++) {
            ml0 = fmaxf(ml0, fmaxf(sacc[j][0], sacc[j][1]));
            ml1 = fmaxf(ml1, fmaxf(sacc[j][2], sacc[j][3]));
        }
        ml0 = fmaxf(ml0, __shfl_xor_sync(0xffffffffu, ml0, 1));
        ml0 = fmaxf(ml0, __shfl_xor_sync(0xffffffffu, ml0, 2));
        ml1 = fmaxf(ml1, __shfl_xor_sync(0xffffffffu, ml1, 1));
        ml1 = fmaxf(ml1, __shfl_xor_sync(0xffffffffu, ml1, 2));

        const float mn0 = fmaxf(m0, ml0), mn1 = fmaxf(m1, ml1);
        const float fac0 = __expf(m0 - mn0), fac1 = __expf(m1 - mn1);
        float ls0 = 0.0f, ls1 = 0.0f;
        #pragma unroll
        for (int j = 0; j < 8; j++) {
            float p0 = __expf(sacc[j][0] - mn0);
            float p1 = __expf(sacc[j][1] - mn0);
            float p2 = __expf(sacc[j][2] - mn1);
            float p3 = __expf(sacc[j][3] - mn1);
            sacc[j][0] = p0; sacc[j][1] = p1; sacc[j][2] = p2; sacc[j][3] = p3;
            ls0 += p0 + p1; ls1 += p2 + p3;
        }
        ls0 += __shfl_xor_sync(0xffffffffu, ls0, 1);
        ls0 += __shfl_xor_sync(0xffffffffu, ls0, 2);
        ls1 += __shfl_xor_sync(0xffffffffu, ls1, 1);
        ls1 += __shfl_xor_sync(0xffffffffu, ls1, 2);
        l0 = l0 * fac0 + ls0;
        l1 = l1 * fac1 + ls1;
        m0 = mn0; m1 = mn1;

        #pragma unroll
        for (int j = 0; j < 8; j++) {
            oacc[j][0] *= fac0; oacc[j][1] *= fac0;
            oacc[j][2] *= fac1; oacc[j][3] *= fac1;
        }

        // ---- O += P V : D-frag pairs ARE the A-frag pairs (no shuffles) ----
        #pragma unroll
        for (int ks = 0; ks < 4; ks++) {
            uint32_t phi[4], plo[4];
            split_bf2(sacc[2 * ks][0],     sacc[2 * ks][1],     phi[0], plo[0]);
            split_bf2(sacc[2 * ks][2],     sacc[2 * ks][3],     phi[1], plo[1]);
            split_bf2(sacc[2 * ks + 1][0], sacc[2 * ks + 1][1], phi[2], plo[2]);
            split_bf2(sacc[2 * ks + 1][2], sacc[2 * ks + 1][3], phi[3], plo[3]);
            const uint32_t c1x = ((uint32_t)(8 * ks + lc)) ^ xmask;
            const uint32_t c2x = ((uint32_t)(8 * ks + lc + 4)) ^ xmask;
            #pragma unroll
            for (int j = 0; j < 8; j++) {
                const uint32_t nb = (uint32_t)(8 * j + lr) * 32;
                uint32_t bvh[2] = { Vhi[nb + c1x], Vhi[nb + c2x] };
                mma_bf16(oacc[j], phi, bvh);
                mma_bf16(oacc[j], plo, bvh);
                uint32_t bvl[2] = { Vlo[nb + c1x], Vlo[nb + c2x] };
                mma_bf16(oacc[j], phi, bvl);
            }
        }
    }

    // ---- Write O, normalized ----
    const float inv0 = 1.0f / l0, inv1 = 1.0f / l1;
    const int row = q0 + 16 * w + lr;
    float* ob0 = out + ((size_t)(b * SEQ + row)) * HIDDEN + h * HS;
    float* ob1 = out + ((size_t)(b * SEQ + row + 8)) * HIDDEN + h * HS;
    #pragma unroll
    for (int j = 0; j < 8; j++) {
        const int c = 8 * j + 2 * lc;
        *(float2*)(ob0 + c) = make_float2(oacc[j][0] * inv0, oacc[j][1] * inv0);
        *(float2*)(ob1 + c) = make_float2(oacc[j][2] * inv1, oacc[j][3] * inv1);
    }
}

// ---------------------------------------------------------------------------
// Launch
// ---------------------------------------------------------------------------
extern "C" void kernel_launch(void* const* d_in, const int* in_sizes, int n_in,
                              void* d_out, int out_size) {
    const float* x    = (const float*)d_in[0];
    const float* W    = (const float*)d_in[1];
    const float* bias = (const float*)d_in[2];
    float* out = (float*)d_out;

    cudaFuncSetAttribute(qkv_gemm_tc,
                         cudaFuncAttributeMaxDynamicSharedMemorySize,
                         GEMM_SMEM_BYTES);
    qkv_gemm_tc<<<dim3(N_COLS / 128, M_ROWS / 128), 256, GEMM_SMEM_BYTES>>>(
        x, W, bias);

    cudaFuncSetAttribute(attn_mma,
                         cudaFuncAttributeMaxDynamicSharedMemorySize,
                         ATT_SMEM_BYTES);
    attn_mma<<<dim3(SEQ / 128, N_HEADS, BATCH), 256, ATT_SMEM_BYTES>>>(out);
}

// round 10
// speedup vs baseline: 1.0069x; 1.0069x over previous
#include <cuda_runtime.h>
#include <cuda_bf16.h>
#include <cuda_fp16.h>
#include <cstdint>
#include <math.h>

#define N_HEADS 16
#define HIDDEN  1024
#define HS      64
#define BATCH   2
#define SEQ     2048
#define M_ROWS  (BATCH * SEQ)      // 4096
#define N_COLS  (3 * HIDDEN)       // 3072

// Scratch QKV, flat [u=2s+b][h][...]:
//   Q (u=0,1) and K (u=2,3): [t][d] row-major
//   V (u=4,5):               [d][t] row-major  (V^T, for bf16 mma B operand)
__device__ float g_qkv[(size_t)6 * N_HEADS * SEQ * HS];

// ---------------------------------------------------------------------------
// Helpers
// ---------------------------------------------------------------------------
__device__ __forceinline__ uint32_t smem_u32(const void* p) {
    uint32_t a;
    asm("{ .reg .u64 t; cvta.to.shared.u64 t, %1; cvt.u32.u64 %0, t; }"
        : "=r"(a) : "l"(p));
    return a;
}
__device__ __forceinline__ void mma_fp16(float* d, const uint32_t* a,
                                         const uint32_t* b) {
    asm volatile(
        "mma.sync.aligned.m16n8k16.row.col.f32.f16.f16.f32 "
        "{%0,%1,%2,%3}, {%4,%5,%6,%7}, {%8,%9}, {%0,%1,%2,%3};"
        : "+f"(d[0]), "+f"(d[1]), "+f"(d[2]), "+f"(d[3])
        : "r"(a[0]), "r"(a[1]), "r"(a[2]), "r"(a[3]),
          "r"(b[0]), "r"(b[1]));
}
__device__ __forceinline__ void mma_bf16(float* d, const uint32_t* a,
                                         const uint32_t* b) {
    asm volatile(
        "mma.sync.aligned.m16n8k16.row.col.f32.bf16.bf16.f32 "
        "{%0,%1,%2,%3}, {%4,%5,%6,%7}, {%8,%9}, {%0,%1,%2,%3};"
        : "+f"(d[0]), "+f"(d[1]), "+f"(d[2]), "+f"(d[3])
        : "r"(a[0]), "r"(a[1]), "r"(a[2]), "r"(a[3]),
          "r"(b[0]), "r"(b[1]));
}
__device__ __forceinline__ uint32_t pack_h2(float x, float y) {
    __half2 h = __floats2half2_rn(x, y);
    return *reinterpret_cast<uint32_t*>(&h);
}
// Split (x,y) into bf16x2 hi and bf16x2 lo (residual). Low half = x (= lower k).
__device__ __forceinline__ void split_bf2(float x, float y,
                                          uint32_t& hi, uint32_t& lo) {
    __nv_bfloat16 hx = __float2bfloat16_rn(x);
    __nv_bfloat16 hy = __float2bfloat16_rn(y);
    __nv_bfloat162 hp; hp.x = hx; hp.y = hy;
    hi = *reinterpret_cast<uint32_t*>(&hp);
    __nv_bfloat162 lp;
    lp.x = __float2bfloat16_rn(x - __bfloat162float(hx));
    lp.y = __float2bfloat16_rn(y - __bfloat162float(hy));
    lo = *reinterpret_cast<uint32_t*>(&lp);
}
__device__ __forceinline__ void cp16(uint32_t dst, const void* src) {
    asm volatile("cp.async.cg.shared.global [%0], [%1], 16;"
                 :: "r"(dst), "l"(src) : "memory");
}
#define CP_COMMIT() asm volatile("cp.async.commit_group;" ::: "memory")
#define CP_WAIT1()  asm volatile("cp.async.wait_group 1;" ::: "memory")
#define CP_WAIT0()  asm volatile("cp.async.wait_group 0;" ::: "memory")

// ---------------------------------------------------------------------------
// Kernel 1: QKV GEMM via mma.sync fp16 m16n8k16.
// 3-stage cp.async pipeline, ONE __syncthreads per k-iteration:
//   top-of-iter sync (a) publishes stage it%3 to all warps, (b) proves every
//   warp consumed stage (it-1)%3 == (it+2)%3, so the next cp.async can issue
//   into it without a second barrier. One commit_group per iter (empty at
//   tail) keeps wait_group arithmetic exact.
// Epilogue: bias + reshape scatter (g = 3r + c/1024; e = c%1024;
// u=g>>11; t=g&2047; h=e&15; d=e>>4); V third written d-major ([d][t]).
// ---------------------------------------------------------------------------
#define GBK   32
#define GNIT  (HIDDEN / GBK)          // 32
#define CSTR  132
#define ASTAGE 4096                   // floats per A stage
#define BSTAGE 4096                   // floats per B stage
#define BBASE  (3 * ASTAGE)           // B stages start (floats)
#define GEMM_SMEM_BYTES (6 * 4096 * 4)   // 98304 >= epilogue's 67584

// Element accessors for the swizzled fp32 tiles
__device__ __forceinline__ float2 lda2(const float* Ab, int r, int k) {
    uint32_t off = (uint32_t)r * 32 + ((((uint32_t)k) & ~3u) ^ (((uint32_t)(r & 7)) << 2))
                 + ((uint32_t)k & 3u);
    return *(const float2*)(Ab + off);
}
__device__ __forceinline__ float ldb1(const float* Bb, int kk, int n) {
    uint32_t off = (uint32_t)kk * 128 + ((((uint32_t)n) & ~3u) ^ (((uint32_t)(kk & 3)) << 3))
                 + ((uint32_t)n & 3u);
    return Bb[off];
}

__global__ void __launch_bounds__(256, 2) qkv_gemm_tc(
    const float* __restrict__ x, const float* __restrict__ W,
    const float* __restrict__ bias)
{
    extern __shared__ float smf[];
    const uint32_t sbase = smem_u32(smf);
    const int tid  = threadIdx.x;
    const int lane = tid & 31;
    const int wid  = tid >> 5;
    const int wm   = wid & 1;
    const int wn   = wid >> 1;
    const int m0 = blockIdx.y * 128, n0 = blockIdx.x * 128;

    const int a_row = tid >> 3;
    const int a_k4  = (tid & 7) << 2;
    const int b_krw = tid >> 5;
    const int b_n4  = (tid & 31) << 2;
    const float* Ag = x + (size_t)(m0 + a_row) * HIDDEN + a_k4;
    const float* Bg = W + (size_t)b_krw * N_COLS + n0 + b_n4;
    const uint32_t a_st = a_row * 32 + (a_k4 ^ (((uint32_t)(a_row & 7)) << 2));
    const uint32_t b_st = b_krw * 128 + (b_n4 ^ (((uint32_t)(b_krw & 3)) << 3));

    const int lr = lane >> 2, lc = lane & 3;

    float acc[4][4][4] = {};

    // Prologue: stages 0 and 1, one commit group each
    #pragma unroll
    for (int s = 0; s < 2; s++) {
        #pragma unroll
        for (int i = 0; i < 4; i++) {
            cp16(sbase + (s * ASTAGE + a_st + i * 1024) * 4,
                 Ag + s * GBK + (size_t)i * 32 * HIDDEN);
            cp16(sbase + (BBASE + s * BSTAGE + b_st + i * 1024) * 4,
                 Bg + (size_t)s * GBK * N_COLS + (size_t)i * 8 * N_COLS);
        }
        CP_COMMIT();
    }

    int stage = 0;
    for (int it = 0; it < GNIT; ++it) {
        CP_WAIT1();          // group carrying stage `it` complete
        __syncthreads();     // publish stage; prove stage (it+2)%3 consumers done

        const float* Ab = smf + stage * ASTAGE;
        const float* Bb = smf + BBASE + stage * BSTAGE;
        #pragma unroll
        for (int ks = 0; ks < 2; ks++) {          // two k16 steps per k32 tile
            const int kb = ks * 16;
            const int k1 = kb + 2 * lc;           // A k-pair 1
            const int k2 = k1 + 8;                // A k-pair 2
            uint32_t af[4][4], bf[4][2];
            #pragma unroll
            for (int mf = 0; mf < 4; mf++) {
                const int r = wm * 64 + mf * 16 + lr;
                float2 p0 = lda2(Ab, r, k1);
                float2 p1 = lda2(Ab, r + 8, k1);
                float2 p2 = lda2(Ab, r, k2);
                float2 p3 = lda2(Ab, r + 8, k2);
                af[mf][0] = pack_h2(p0.x, p0.y);
                af[mf][1] = pack_h2(p1.x, p1.y);
                af[mf][2] = pack_h2(p2.x, p2.y);
                af[mf][3] = pack_h2(p3.x, p3.y);
            }
            #pragma unroll
            for (int nf = 0; nf < 4; nf++) {
                const int n = wn * 32 + nf * 8 + lr;
                bf[nf][0] = pack_h2(ldb1(Bb, k1, n), ldb1(Bb, k1 + 1, n));
                bf[nf][1] = pack_h2(ldb1(Bb, k2, n), ldb1(Bb, k2 + 1, n));
            }
            #pragma unroll
            for (int mf = 0; mf < 4; mf++)
                #pragma unroll
                for (int nf = 0; nf < 4; nf++)
                    mma_fp16(acc[mf][nf], af[mf], bf[nf]);
        }

        // Refill stage (it+2)%3 — its previous consumers finished before the
        // sync above. Commit unconditionally (empty group at tail is fine).
        if (it + 2 < GNIT) {
            const int ns = (stage + 2 >= 3) ? stage - 1 : stage + 2;
            const float* Agn = Ag + (it + 2) * GBK;
            const float* Bgn = Bg + (size_t)(it + 2) * GBK * N_COLS;
            #pragma unroll
            for (int i = 0; i < 4; i++) {
                cp16(sbase + (ns * ASTAGE + a_st + i * 1024) * 4,
                     Agn + (size_t)i * 32 * HIDDEN);
                cp16(sbase + (BBASE + ns * BSTAGE + b_st + i * 1024) * 4,
                     Bgn + (size_t)i * 8 * N_COLS);
            }
        }
        CP_COMMIT();

        stage = (stage + 1 == 3) ? 0 : stage + 1;
    }
    __syncthreads();   // all compute done before smem is reused for epilogue

    // ---- Epilogue via smem ----
    float* Cs = smf;
    #pragma unroll
    for (int mf = 0; mf < 4; mf++) {
        const int r = wm * 64 + mf * 16 + lr;
        #pragma unroll
        for (int nf = 0; nf < 4; nf++) {
            const int c = wn * 32 + nf * 8 + 2 * lc;
            *(float2*)&Cs[r * CSTR + c]       = make_float2(acc[mf][nf][0], acc[mf][nf][1]);
            *(float2*)&Cs[(r + 8) * CSTR + c] = make_float2(acc[mf][nf][2], acc[mf][nf][3]);
        }
    }
    __syncthreads();

    {
        const int rr = tid >> 1;
        const int half = tid & 1;
        const int r = m0 + rr;
        const int g = 3 * r + (n0 >> 10);
        const int u = g >> 11, t = g & 2047;
        const int d0 = (n0 & 1023) >> 4;
        const bool isV = ((u >> 1) == 2);
        #pragma unroll
        for (int j = 0; j < 8; j++) {
            const int hh = half * 8 + j;
            float o[8];
            #pragma unroll
            for (int e = 0; e < 8; e++)
                o[e] = Cs[rr * CSTR + hh + 16 * e] + __ldg(&bias[n0 + hh + 16 * e]);
            float* base = g_qkv + (size_t)(u * 16 + hh) * (SEQ * HS);
            if (isV) {
                // V stored d-major: [d][t]
                #pragma unroll
                for (int e = 0; e < 8; e++)
                    base[(size_t)(d0 + e) * SEQ + t] = o[e];
            } else {
                float* dst = base + (size_t)t * HS + d0;
                *(float4*)dst       = make_float4(o[0], o[1], o[2], o[3]);
                *(float4*)(dst + 4) = make_float4(o[4], o[5], o[6], o[7]);
            }
        }
    }
}

// ---------------------------------------------------------------------------
// Kernel 2: flash attention via mma.sync bf16 m16n8k16, split-2 precision.
// (unchanged from R8/R9 — measured 222-235us, near the fallback HMMA ceiling)
// ---------------------------------------------------------------------------
#define ATT_SMEM_BYTES (16384 * 4)

__global__ void __launch_bounds__(256, 2) attn_mma(float* __restrict__ out) {
    extern __shared__ uint32_t sm[];
    uint32_t* Qhi = sm;                 // 4096
    uint32_t* Qlo = sm + 4096;          // 4096
    uint32_t* Khi = sm + 8192;          // 2048
    uint32_t* Klo = sm + 10240;         // 2048
    uint32_t* Vhi = sm + 12288;         // 2048
    uint32_t* Vlo = sm + 14336;         // 2048

    const int tid  = threadIdx.x;
    const int lane = tid & 31;
    const int w    = tid >> 5;          // warp 0..7, rows [16w,16w+16)
    const int lr   = lane >> 2, lc = lane & 3;
    const int qtile = (int)(gridDim.x - 1) - (int)blockIdx.x;  // long CTAs first
    const int h = blockIdx.y, b = blockIdx.z;
    const int q0 = qtile * 128;

    const float* qg  = g_qkv + (size_t)(b * 16 + h) * (SEQ * HS);        // [t][d]
    const float* kg  = g_qkv + (size_t)((2 + b) * 16 + h) * (SEQ * HS);  // [t][d]
    const float* vtg = g_qkv + (size_t)((4 + b) * 16 + h) * (SEQ * HS);  // [d][t]

    // ---- Load Q tile (scaled by 2^-3, exact), split-2 into bf16x2 pairs ----
    #pragma unroll
    for (int i = 0; i < 8; i++) {
        int f = tid + i * 256;
        int r = f >> 4, d4 = (f & 15) << 2;
        float4 v = *(const float4*)(qg + (size_t)(q0 + r) * HS + d4);
        v.x *= 0.125f; v.y *= 0.125f; v.z *= 0.125f; v.w *= 0.125f;
        uint32_t idx = r * 32 + (((uint32_t)d4 >> 1) ^ (((uint32_t)(r & 7)) << 2));
        uint2 hi, lo;
        split_bf2(v.x, v.y, hi.x, lo.x);
        split_bf2(v.z, v.w, hi.y, lo.y);
        *(uint2*)&Qhi[idx] = hi;
        *(uint2*)&Qlo[idx] = lo;
    }

    float oacc[8][4];
    #pragma unroll
    for (int j = 0; j < 8; j++)
        #pragma unroll
        for (int k = 0; k < 4; k++) oacc[j][k] = 0.0f;
    float m0 = -1e30f, m1 = -1e30f, l0 = 0.0f, l1 = 0.0f;

    const int st_r  = tid >> 4;               // 0..15 (+16i)
    const int st_c4 = (tid & 15) << 2;        // 0..60
    const uint32_t xmask = (uint32_t)(lane >> 2 & 7) << 2;  // = lr<<2

    const int nkt = 2 * qtile + 2;
    for (int kt = 0; kt < nkt; kt++) {
        const int k0g = kt * 64;

        // ---- K quad: LDG issued pre-sync ----
        float4 kreg[4];
        uint32_t kidx[4];
        #pragma unroll
        for (int i = 0; i < 4; i++) {
            int rr = st_r + i * 16;
            kreg[i] = *(const float4*)(kg + (size_t)(k0g + rr) * HS + st_c4);
            kidx[i] = rr * 32 + (((uint32_t)st_c4 >> 1) ^ (((uint32_t)(rr & 7)) << 2));
        }
        __syncthreads();   // prev-tile consumers done
        #pragma unroll
        for (int i = 0; i < 4; i++) {
            uint2 hi, lo;
            split_bf2(kreg[i].x, kreg[i].y, hi.x, lo.x);
            split_bf2(kreg[i].z, kreg[i].w, hi.y, lo.y);
            *(uint2*)&Khi[kidx[i]] = hi;
            *(uint2*)&Klo[kidx[i]] = lo;
        }
        // ---- V^T quad ----
        float4 vreg[4];
        #pragma unroll
        for (int i = 0; i < 4; i++)
            vreg[i] = *(const float4*)(vtg + (size_t)(st_r + i * 16) * SEQ + k0g + st_c4);
        #pragma unroll
        for (int i = 0; i < 4; i++) {
            uint2 hi, lo;
            split_bf2(vreg[i].x, vreg[i].y, hi.x, lo.x);
            split_bf2(vreg[i].z, vreg[i].w, hi.y, lo.y);
            *(uint2*)&Vhi[kidx[i]] = hi;
            *(uint2*)&Vlo[kidx[i]] = lo;
        }
        __syncthreads();   // tiles visible

        // Full-skip: all cols of this tile above all rows of this warp
        if (k0g > q0 + 16 * w + 15) continue;

        // ---- S = Q K^T (bf16 split-2, 3-term) ----
        float sacc[8][4];
        #pragma unroll
        for (int j = 0; j < 8; j++)
            #pragma unroll
            for (int k = 0; k < 4; k++) sacc[j][k] = 0.0f;

        const int r = 16 * w + lr;
        const uint32_t qbase = r * 32;
        #pragma unroll
        for (int ks = 0; ks < 4; ks++) {
            const uint32_t c1x = ((uint32_t)(8 * ks + lc)) ^ xmask;
            const uint32_t c2x = ((uint32_t)(8 * ks + lc + 4)) ^ xmask;
            uint32_t ahi[4], alo[4];
            ahi[0] = Qhi[qbase + c1x];       alo[0] = Qlo[qbase + c1x];
            ahi[1] = Qhi[qbase + 256 + c1x]; alo[1] = Qlo[qbase + 256 + c1x];
            ahi[2] = Qhi[qbase + c2x];       alo[2] = Qlo[qbase + c2x];
            ahi[3] = Qhi[qbase + 256 + c2x]; alo[3] = Qlo[qbase + 256 + c2x];
            #pragma unroll
            for (int j = 0; j < 8; j++) {
                const uint32_t nb = (uint32_t)(8 * j + lr) * 32;
                uint32_t bh[2] = { Khi[nb + c1x], Khi[nb + c2x] };
                mma_bf16(sacc[j], ahi, bh);
                mma_bf16(sacc[j], alo, bh);
                uint32_t bl[2] = { Klo[nb + c1x], Klo[nb + c2x] };
                mma_bf16(sacc[j], ahi, bl);
            }
        }

        // ---- Causal mask (only near diagonal) ----
        const int row0 = q0 + 16 * w + lr;
        if (k0g + 63 > q0 + 16 * w) {
            #pragma unroll
            for (int j = 0; j < 8; j++) {
                const int c0 = k0g + 8 * j + 2 * lc;
                if (c0 > row0)         sacc[j][0] = -1e30f;
                if (c0 + 1 > row0)     sacc[j][1] = -1e30f;
                if (c0 > row0 + 8)     sacc[j][2] = -1e30f;
                if (c0 + 1 > row0 + 8) sacc[j][3] = -1e30f;
            }
        }

        // ---- Online softmax (registers + quad shuffles) ----
        float ml0 = -1e30f, ml1 = -1e30f;
        #pragma unroll
        for (int j = 0; j < 8; j++) {
            ml0 = fmaxf(ml0, fmaxf(sacc[j][0], sacc[j][1]));
            ml1 = fmaxf(ml1, fmaxf(sacc[j][2], sacc[j][3]));
        }
        ml0 = fmaxf(ml0, __shfl_xor_sync(0xffffffffu, ml0, 1));
        ml0 = fmaxf(ml0, __shfl_xor_sync(0xffffffffu, ml0, 2));
        ml1 = fmaxf(ml1, __shfl_xor_sync(0xffffffffu, ml1, 1));
        ml1 = fmaxf(ml1, __shfl_xor_sync(0xffffffffu, ml1, 2));

        const float mn0 = fmaxf(m0, ml0), mn1 = fmaxf(m1, ml1);
        const float fac0 = __expf(m0 - mn0), fac1 = __expf(m1 - mn1);
        float ls0 = 0.0f, ls1 = 0.0f;
        #pragma unroll
        for (int j = 0; j < 8; j++) {
            float p0 = __expf(sacc[j][0] - mn0);
            float p1 = __expf(sacc[j][1] - mn0);
            float p2 = __expf(sacc[j][2] - mn1);
            float p3 = __expf(sacc[j][3] - mn1);
            sacc[j][0] = p0; sacc[j][1] = p1; sacc[j][2] = p2; sacc[j][3] = p3;
            ls0 += p0 + p1; ls1 += p2 + p3;
        }
        ls0 += __shfl_xor_sync(0xffffffffu, ls0, 1);
        ls0 += __shfl_xor_sync(0xffffffffu, ls0, 2);
        ls1 += __shfl_xor_sync(0xffffffffu, ls1, 1);
        ls1 += __shfl_xor_sync(0xffffffffu, ls1, 2);
        l0 = l0 * fac0 + ls0;
        l1 = l1 * fac1 + ls1;
        m0 = mn0; m1 = mn1;

        #pragma unroll
        for (int j = 0; j < 8; j++) {
            oacc[j][0] *= fac0; oacc[j][1] *= fac0;
            oacc[j][2] *= fac1; oacc[j][3] *= fac1;
        }

        // ---- O += P V : D-frag pairs ARE the A-frag pairs (no shuffles) ----
        #pragma unroll
        for (int ks = 0; ks < 4; ks++) {
            uint32_t phi[4], plo[4];
            split_bf2(sacc[2 * ks][0],     sacc[2 * ks][1],     phi[0], plo[0]);
            split_bf2(sacc[2 * ks][2],     sacc[2 * ks][3],     phi[1], plo[1]);
            split_bf2(sacc[2 * ks + 1][0], sacc[2 * ks + 1][1], phi[2], plo[2]);
            split_bf2(sacc[2 * ks + 1][2], sacc[2 * ks + 1][3], phi[3], plo[3]);
            const uint32_t c1x = ((uint32_t)(8 * ks + lc)) ^ xmask;
            const uint32_t c2x = ((uint32_t)(8 * ks + lc + 4)) ^ xmask;
            #pragma unroll
            for (int j = 0; j < 8; j++) {
                const uint32_t nb = (uint32_t)(8 * j + lr) * 32;
                uint32_t bvh[2] = { Vhi[nb + c1x], Vhi[nb + c2x] };
                mma_bf16(oacc[j], phi, bvh);
                mma_bf16(oacc[j], plo, bvh);
                uint32_t bvl[2] = { Vlo[nb + c1x], Vlo[nb + c2x] };
                mma_bf16(oacc[j], phi, bvl);
            }
        }
    }

    // ---- Write O, normalized ----
    const float inv0 = 1.0f / l0, inv1 = 1.0f / l1;
    const int row = q0 + 16 * w + lr;
    float* ob0 = out + ((size_t)(b * SEQ + row)) * HIDDEN + h * HS;
    float* ob1 = out + ((size_t)(b * SEQ + row + 8)) * HIDDEN + h * HS;
    #pragma unroll
    for (int j = 0; j < 8; j++) {
        const int c = 8 * j + 2 * lc;
        *(float2*)(ob0 + c) = make_float2(oacc[j][0] * inv0, oacc[j][1] * inv0);
        *(float2*)(ob1 + c) = make_float2(oacc[j][2] * inv1, oacc[j][3] * inv1);
    }
}

// ---------------------------------------------------------------------------
// Launch
// ---------------------------------------------------------------------------
extern "C" void kernel_launch(void* const* d_in, const int* in_sizes, int n_in,
                              void* d_out, int out_size) {
    const float* x    = (const float*)d_in[0];
    const float* W    = (const float*)d_in[1];
    const float* bias = (const float*)d_in[2];
    float* out = (float*)d_out;

    cudaFuncSetAttribute(qkv_gemm_tc,
                         cudaFuncAttributeMaxDynamicSharedMemorySize,
                         GEMM_SMEM_BYTES);
    qkv_gemm_tc<<<dim3(N_COLS / 128, M_ROWS / 128), 256, GEMM_SMEM_BYTES>>>(
        x, W, bias);

    cudaFuncSetAttribute(attn_mma,
                         cudaFuncAttributeMaxDynamicSharedMemorySize,
                         ATT_SMEM_BYTES);
    attn_mma<<<dim3(SEQ / 128, N_HEADS, BATCH), 256, ATT_SMEM_BYTES>>>(out);
}

// round 12
// speedup vs baseline: 1.2683x; 1.2596x over previous
#include <cuda_runtime.h>
#include <cuda_bf16.h>
#include <cuda_fp16.h>
#include <cstdint>
#include <math.h>

#define N_HEADS 16
#define HIDDEN  1024
#define HS      64
#define BATCH   2
#define SEQ     2048
#define M_ROWS  (BATCH * SEQ)      // 4096
#define N_COLS  (3 * HIDDEN)       // 3072

// Scratch QKV, flat [u=2s+b][h][...]:
//   Q (u=0,1) and K (u=2,3): [t][d] row-major
//   V (u=4,5):               [d][t] row-major  (V^T, for bf16 mma B operand)
__device__ float g_qkv[(size_t)6 * N_HEADS * SEQ * HS];
// fp16 copies of the GEMM inputs (prepass output)
__device__ __half g_xh[(size_t)M_ROWS * HIDDEN];
__device__ __half g_wh[(size_t)HIDDEN * N_COLS];

// ---------------------------------------------------------------------------
// Helpers
// ---------------------------------------------------------------------------
__device__ __forceinline__ uint32_t smem_u32(const void* p) {
    uint32_t a;
    asm("{ .reg .u64 t; cvta.to.shared.u64 t, %1; cvt.u32.u64 %0, t; }"
        : "=r"(a) : "l"(p));
    return a;
}
__device__ __forceinline__ void mma_fp16(float* d, const uint32_t* a,
                                         const uint32_t* b) {
    asm volatile(
        "mma.sync.aligned.m16n8k16.row.col.f32.f16.f16.f32 "
        "{%0,%1,%2,%3}, {%4,%5,%6,%7}, {%8,%9}, {%0,%1,%2,%3};"
        : "+f"(d[0]), "+f"(d[1]), "+f"(d[2]), "+f"(d[3])
        : "r"(a[0]), "r"(a[1]), "r"(a[2]), "r"(a[3]),
          "r"(b[0]), "r"(b[1]));
}
__device__ __forceinline__ void mma_bf16(float* d, const uint32_t* a,
                                         const uint32_t* b) {
    asm volatile(
        "mma.sync.aligned.m16n8k16.row.col.f32.bf16.bf16.f32 "
        "{%0,%1,%2,%3}, {%4,%5,%6,%7}, {%8,%9}, {%0,%1,%2,%3};"
        : "+f"(d[0]), "+f"(d[1]), "+f"(d[2]), "+f"(d[3])
        : "r"(a[0]), "r"(a[1]), "r"(a[2]), "r"(a[3]),
          "r"(b[0]), "r"(b[1]));
}
__device__ __forceinline__ void ldsm_x4(uint32_t& r0, uint32_t& r1,
                                        uint32_t& r2, uint32_t& r3,
                                        uint32_t addr) {
    asm volatile("ldmatrix.sync.aligned.m8n8.x4.shared.b16 {%0,%1,%2,%3}, [%4];"
                 : "=r"(r0), "=r"(r1), "=r"(r2), "=r"(r3) : "r"(addr));
}
__device__ __forceinline__ void ldsm_x4_t(uint32_t& r0, uint32_t& r1,
                                          uint32_t& r2, uint32_t& r3,
                                          uint32_t addr) {
    asm volatile("ldmatrix.sync.aligned.m8n8.x4.trans.shared.b16 {%0,%1,%2,%3}, [%4];"
                 : "=r"(r0), "=r"(r1), "=r"(r2), "=r"(r3) : "r"(addr));
}
// Split (x,y) into bf16x2 hi and bf16x2 lo (residual). Low half = x (= lower k).
__device__ __forceinline__ void split_bf2(float x, float y,
                                          uint32_t& hi, uint32_t& lo) {
    __nv_bfloat16 hx = __float2bfloat16_rn(x);
    __nv_bfloat16 hy = __float2bfloat16_rn(y);
    __nv_bfloat162 hp; hp.x = hx; hp.y = hy;
    hi = *reinterpret_cast<uint32_t*>(&hp);
    __nv_bfloat162 lp;
    lp.x = __float2bfloat16_rn(x - __bfloat162float(hx));
    lp.y = __float2bfloat16_rn(y - __bfloat162float(hy));
    lo = *reinterpret_cast<uint32_t*>(&lp);
}
__device__ __forceinline__ void cp16(uint32_t dst, const void* src) {
    asm volatile("cp.async.cg.shared.global [%0], [%1], 16;"
                 :: "r"(dst), "l"(src) : "memory");
}
#define CP_COMMIT() asm volatile("cp.async.commit_group;" ::: "memory")
#define CP_WAIT1()  asm volatile("cp.async.wait_group 1;" ::: "memory")
#define CP_WAIT0()  asm volatile("cp.async.wait_group 0;" ::: "memory")

// ---------------------------------------------------------------------------
// Kernel 0: fp32 -> fp16 prepass for x and W (single rounding, same values
// previous rounds produced at fragment time -> identical numerics).
// ---------------------------------------------------------------------------
#define NX4 ((size_t)M_ROWS * HIDDEN / 4)   // 1048576
#define NW4 ((size_t)HIDDEN * N_COLS / 4)   // 786432

__global__ void __launch_bounds__(256) cvt_half(const float* __restrict__ x,
                                                const float* __restrict__ W) {
    size_t i = (size_t)blockIdx.x * 256 + threadIdx.x;
    if (i < NX4) {
        float4 v = ((const float4*)x)[i];
        __half2* dst = (__half2*)(g_xh + i * 4);
        dst[0] = __floats2half2_rn(v.x, v.y);
        dst[1] = __floats2half2_rn(v.z, v.w);
    } else if (i < NX4 + NW4) {
        size_t j = i - NX4;
        float4 v = ((const float4*)W)[j];
        __half2* dst = (__half2*)(g_wh + j * 4);
        dst[0] = __floats2half2_rn(v.x, v.y);
        dst[1] = __floats2half2_rn(v.z, v.w);
    }
}

// ---------------------------------------------------------------------------
// Kernel 1: QKV GEMM via mma.sync fp16 m16n8k16 with ldmatrix fragments.
// fp16 tiles staged by cp.async, 2-stage double buffer.
// A tile: [128 m][32 k] halfs, row stride 80B (pad) -> conflict-free x4.
// B tile: [32 k][128 n] halfs, 256B rows, store swizzle col^((k&7)<<4);
//   load applies the SAME xor to the FULL column byte offset (R11 bug:
//   nblk offset was added after the xor — xor/add don't commute on bit 5).
// Epilogue: bias + reshape scatter (g = 3r + c/1024; e = c%1024;
// u=g>>11; t=g&2047; h=e&15; d=e>>4); V third written d-major ([d][t]).
// ---------------------------------------------------------------------------
#define GBK   32
#define GNIT  (HIDDEN / GBK)          // 32
#define CSTR  132
#define AST_B 10240                   // A stage bytes (128 * 80)
#define STG_B 18432                   // A (10240) + B (8192)
#define GEMM_SMEM_BYTES (CSTR * 128 * 4)   // 67584 >= 2*18432

__global__ void __launch_bounds__(256, 2) qkv_gemm_tc(const float* __restrict__ bias)
{
    extern __shared__ char smc[];
    const uint32_t sbase = smem_u32(smc);
    const int tid  = threadIdx.x;
    const int lane = tid & 31;
    const int wid  = tid >> 5;
    const int wm   = wid & 1;
    const int wn   = wid >> 1;
    const int m0 = blockIdx.y * 128, n0 = blockIdx.x * 128;
    const int lr = lane >> 2, lc = lane & 3;

    // cp.async mapping: 2 A-chunks + 2 B-chunks (16B each) per thread
    uint32_t a_dst[2], b_dst[2];
    const __half* a_src[2];
    const __half* b_src[2];
    #pragma unroll
    for (int i = 0; i < 2; i++) {
        int id = tid + i * 256;
        int am = id >> 2, ac = id & 3;                 // A: 128 rows x 4 chunks
        a_dst[i] = (uint32_t)(am * 80 + ac * 16);
        a_src[i] = g_xh + (size_t)(m0 + am) * HIDDEN + ac * 8;
        int bk = id >> 4, bc = id & 15;                // B: 32 rows x 16 chunks
        b_dst[i] = (uint32_t)(AST_B + bk * 256 + ((bc * 16) ^ ((bk & 7) << 4)));
        b_src[i] = g_wh + (size_t)bk * N_COLS + n0 + bc * 8;
    }

    // ldmatrix lane decomposition (g = matrix index, r = row within matrix)
    const int g = lane >> 3, r = lane & 7;
    const uint32_t a_lane = (uint32_t)((wm * 64 + ((g & 1) << 3) + r) * 80
                                       + (((g >> 1) << 3) << 1));
    const uint32_t b_rowb  = (uint32_t)((((g & 1) << 3) + r) * 256);   // k-row bytes
    const uint32_t b_colh0 = (uint32_t)(wn * 32 + ((g >> 1) << 3));    // n in halfs
    const uint32_t b_xor   = (uint32_t)(r << 4);

    float acc[4][4][4] = {};

    // Prologue: stage 0
    #pragma unroll
    for (int i = 0; i < 2; i++) {
        cp16(sbase + a_dst[i], a_src[i]);
        cp16(sbase + b_dst[i], b_src[i]);
    }
    CP_COMMIT();

    for (int it = 0; it < GNIT; ++it) {
        const uint32_t buf = (uint32_t)(it & 1) * STG_B;
        if (it + 1 < GNIT) {
            const uint32_t nb = (uint32_t)((it + 1) & 1) * STG_B;
            #pragma unroll
            for (int i = 0; i < 2; i++) {
                cp16(sbase + nb + a_dst[i], a_src[i] + (it + 1) * GBK);
                cp16(sbase + nb + b_dst[i], b_src[i] + (size_t)(it + 1) * GBK * N_COLS);
            }
            CP_COMMIT();
            CP_WAIT1();
        } else {
            CP_WAIT0();
        }
        __syncthreads();

        #pragma unroll
        for (int ks = 0; ks < 2; ks++) {
            uint32_t bf[4][2];
            #pragma unroll
            for (int nblk = 0; nblk < 2; nblk++) {
                // FULL column folded in BEFORE the xor (bit-5 overlap fix)
                uint32_t baddr = sbase + buf + AST_B + b_rowb + (uint32_t)(ks * 4096)
                               + ((((b_colh0 + nblk * 16) << 1)) ^ b_xor);
                uint32_t r0, r1, r2, r3;
                ldsm_x4_t(r0, r1, r2, r3, baddr);
                bf[nblk * 2 + 0][0] = r0; bf[nblk * 2 + 0][1] = r1;
                bf[nblk * 2 + 1][0] = r2; bf[nblk * 2 + 1][1] = r3;
            }
            #pragma unroll
            for (int mf = 0; mf < 4; mf++) {
                uint32_t af[4];
                ldsm_x4(af[0], af[1], af[2], af[3],
                        sbase + buf + a_lane + mf * 1280 + ks * 32);
                #pragma unroll
                for (int nf = 0; nf < 4; nf++)
                    mma_fp16(acc[mf][nf], af, bf[nf]);
            }
        }
        __syncthreads();
    }

    // ---- Epilogue via smem ----
    float* Cs = (float*)smc;
    #pragma unroll
    for (int mf = 0; mf < 4; mf++) {
        const int rr = wm * 64 + mf * 16 + lr;
        #pragma unroll
        for (int nf = 0; nf < 4; nf++) {
            const int c = wn * 32 + nf * 8 + 2 * lc;
            *(float2*)&Cs[rr * CSTR + c]       = make_float2(acc[mf][nf][0], acc[mf][nf][1]);
            *(float2*)&Cs[(rr + 8) * CSTR + c] = make_float2(acc[mf][nf][2], acc[mf][nf][3]);
        }
    }
    __syncthreads();

    {
        const int rr = tid >> 1;
        const int half = tid & 1;
        const int rglob = m0 + rr;
        const int gg = 3 * rglob + (n0 >> 10);
        const int u = gg >> 11, t = gg & 2047;
        const int d0 = (n0 & 1023) >> 4;
        const bool isV = ((u >> 1) == 2);
        #pragma unroll
        for (int j = 0; j < 8; j++) {
            const int hh = half * 8 + j;
            float o[8];
            #pragma unroll
            for (int e = 0; e < 8; e++)
                o[e] = Cs[rr * CSTR + hh + 16 * e] + __ldg(&bias[n0 + hh + 16 * e]);
            float* base = g_qkv + (size_t)(u * 16 + hh) * (SEQ * HS);
            if (isV) {
                // V stored d-major: [d][t]
                #pragma unroll
                for (int e = 0; e < 8; e++)
                    base[(size_t)(d0 + e) * SEQ + t] = o[e];
            } else {
                float* dst = base + (size_t)t * HS + d0;
                *(float4*)dst       = make_float4(o[0], o[1], o[2], o[3]);
                *(float4*)(dst + 4) = make_float4(o[4], o[5], o[6], o[7]);
            }
        }
    }
}

// ---------------------------------------------------------------------------
// Kernel 2: flash attention via mma.sync bf16 m16n8k16, split-2 precision.
// (unchanged from R8-R10 — measured 207-235us, near the fallback HMMA ceiling)
// ---------------------------------------------------------------------------
#define ATT_SMEM_BYTES (16384 * 4)

__global__ void __launch_bounds__(256, 2) attn_mma(float* __restrict__ out) {
    extern __shared__ uint32_t sm[];
    uint32_t* Qhi = sm;                 // 4096
    uint32_t* Qlo = sm + 4096;          // 4096
    uint32_t* Khi = sm + 8192;          // 2048
    uint32_t* Klo = sm + 10240;         // 2048
    uint32_t* Vhi = sm + 12288;         // 2048
    uint32_t* Vlo = sm + 14336;         // 2048

    const int tid  = threadIdx.x;
    const int lane = tid & 31;
    const int w    = tid >> 5;          // warp 0..7, rows [16w,16w+16)
    const int lr   = lane >> 2, lc = lane & 3;
    const int qtile = (int)(gridDim.x - 1) - (int)blockIdx.x;  // long CTAs first
    const int h = blockIdx.y, b = blockIdx.z;
    const int q0 = qtile * 128;

    const float* qg  = g_qkv + (size_t)(b * 16 + h) * (SEQ * HS);        // [t][d]
    const float* kg  = g_qkv + (size_t)((2 + b) * 16 + h) * (SEQ * HS);  // [t][d]
    const float* vtg = g_qkv + (size_t)((4 + b) * 16 + h) * (SEQ * HS);  // [d][t]

    // ---- Load Q tile (scaled by 2^-3, exact), split-2 into bf16x2 pairs ----
    #pragma unroll
    for (int i = 0; i < 8; i++) {
        int f = tid + i * 256;
        int r = f >> 4, d4 = (f & 15) << 2;
        float4 v = *(const float4*)(qg + (size_t)(q0 + r) * HS + d4);
        v.x *= 0.125f; v.y *= 0.125f; v.z *= 0.125f; v.w *= 0.125f;
        uint32_t idx = r * 32 + (((uint32_t)d4 >> 1) ^ (((uint32_t)(r & 7)) << 2));
        uint2 hi, lo;
        split_bf2(v.x, v.y, hi.x, lo.x);
        split_bf2(v.z, v.w, hi.y, lo.y);
        *(uint2*)&Qhi[idx] = hi;
        *(uint2*)&Qlo[idx] = lo;
    }

    float oacc[8][4];
    #pragma unroll
    for (int j = 0; j < 8; j++)
        #pragma unroll
        for (int k = 0; k < 4; k++) oacc[j][k] = 0.0f;
    float m0 = -1e30f, m1 = -1e30f, l0 = 0.0f, l1 = 0.0f;

    const int st_r  = tid >> 4;               // 0..15 (+16i)
    const int st_c4 = (tid & 15) << 2;        // 0..60
    const uint32_t xmask = (uint32_t)(lane >> 2 & 7) << 2;  // = lr<<2

    const int nkt = 2 * qtile + 2;
    for (int kt = 0; kt < nkt; kt++) {
        const int k0g = kt * 64;

        // ---- K quad: LDG issued pre-sync ----
        float4 kreg[4];
        uint32_t kidx[4];
        #pragma unroll
        for (int i = 0; i < 4; i++) {
            int rr = st_r + i * 16;
            kreg[i] = *(const float4*)(kg + (size_t)(k0g + rr) * HS + st_c4);
            kidx[i] = rr * 32 + (((uint32_t)st_c4 >> 1) ^ (((uint32_t)(rr & 7)) << 2));
        }
        __syncthreads();   // prev-tile consumers done
        #pragma unroll
        for (int i = 0; i < 4; i++) {
            uint2 hi, lo;
            split_bf2(kreg[i].x, kreg[i].y, hi.x, lo.x);
            split_bf2(kreg[i].z, kreg[i].w, hi.y, lo.y);
            *(uint2*)&Khi[kidx[i]] = hi;
            *(uint2*)&Klo[kidx[i]] = lo;
        }
        // ---- V^T quad ----
        float4 vreg[4];
        #pragma unroll
        for (int i = 0; i < 4; i++)
            vreg[i] = *(const float4*)(vtg + (size_t)(st_r + i * 16) * SEQ + k0g + st_c4);
        #pragma unroll
        for (int i = 0; i < 4; i++) {
            uint2 hi, lo;
            split_bf2(vreg[i].x, vreg[i].y, hi.x, lo.x);
            split_bf2(vreg[i].z, vreg[i].w, hi.y, lo.y);
            *(uint2*)&Vhi[kidx[i]] = hi;
            *(uint2*)&Vlo[kidx[i]] = lo;
        }
        __syncthreads();   // tiles visible

        // Full-skip: all cols of this tile above all rows of this warp
        if (k0g > q0 + 16 * w + 15) continue;

        // ---- S = Q K^T (bf16 split-2, 3-term) ----
        float sacc[8][4];
        #pragma unroll
        for (int j = 0; j < 8; j++)
            #pragma unroll
            for (int k = 0; k < 4; k++) sacc[j][k] = 0.0f;

        const int r = 16 * w + lr;
        const uint32_t qbase = r * 32;
        #pragma unroll
        for (int ks = 0; ks < 4; ks++) {
            const uint32_t c1x = ((uint32_t)(8 * ks + lc)) ^ xmask;
            const uint32_t c2x = ((uint32_t)(8 * ks + lc + 4)) ^ xmask;
            uint32_t ahi[4], alo[4];
            ahi[0] = Qhi[qbase + c1x];       alo[0] = Qlo[qbase + c1x];
            ahi[1] = Qhi[qbase + 256 + c1x]; alo[1] = Qlo[qbase + 256 + c1x];
            ahi[2] = Qhi[qbase + c2x];       alo[2] = Qlo[qbase + c2x];
            ahi[3] = Qhi[qbase + 256 + c2x]; alo[3] = Qlo[qbase + 256 + c2x];
            #pragma unroll
            for (int j = 0; j < 8; j++) {
                const uint32_t nb = (uint32_t)(8 * j + lr) * 32;
                uint32_t bh[2] = { Khi[nb + c1x], Khi[nb + c2x] };
                mma_bf16(sacc[j], ahi, bh);
                mma_bf16(sacc[j], alo, bh);
                uint32_t bl[2] = { Klo[nb + c1x], Klo[nb + c2x] };
                mma_bf16(sacc[j], ahi, bl);
            }
        }

        // ---- Causal mask (only near diagonal) ----
        const int row0 = q0 + 16 * w + lr;
        if (k0g + 63 > q0 + 16 * w) {
            #pragma unroll
            for (int j = 0; j < 8; j++) {
                const int c0 = k0g + 8 * j + 2 * lc;
                if (c0 > row0)         sacc[j][0] = -1e30f;
                if (c0 + 1 > row0)     sacc[j][1] = -1e30f;
                if (c0 > row0 + 8)     sacc[j][2] = -1e30f;
                if (c0 + 1 > row0 + 8) sacc[j][3] = -1e30f;
            }
        }

        // ---- Online softmax (registers + quad shuffles) ----
        float ml0 = -1e30f, ml1 = -1e30f;
        #pragma unroll
        for (int j = 0; j < 8; j++) {
            ml0 = fmaxf(ml0, fmaxf(sacc[j][0], sacc[j][1]));
            ml1 = fmaxf(ml1, fmaxf(sacc[j][2], sacc[j][3]));
        }
        ml0 = fmaxf(ml0, __shfl_xor_sync(0xffffffffu, ml0, 1));
        ml0 = fmaxf(ml0, __shfl_xor_sync(0xffffffffu, ml0, 2));
        ml1 = fmaxf(ml1, __shfl_xor_sync(0xffffffffu, ml1, 1));
        ml1 = fmaxf(ml1, __shfl_xor_sync(0xffffffffu, ml1, 2));

        const float mn0 = fmaxf(m0, ml0), mn1 = fmaxf(m1, ml1);
        const float fac0 = __expf(m0 - mn0), fac1 = __expf(m1 - mn1);
        float ls0 = 0.0f, ls1 = 0.0f;
        #pragma unroll
        for (int j = 0; j < 8; j++) {
            float p0 = __expf(sacc[j][0] - mn0);
            float p1 = __expf(sacc[j][1] - mn0);
            float p2 = __expf(sacc[j][2] - mn1);
            float p3 = __expf(sacc[j][3] - mn1);
            sacc[j][0] = p0; sacc[j][1] = p1; sacc[j][2] = p2; sacc[j][3] = p3;
            ls0 += p0 + p1; ls1 += p2 + p3;
        }
        ls0 += __shfl_xor_sync(0xffffffffu, ls0, 1);
        ls0 += __shfl_xor_sync(0xffffffffu, ls0, 2);
        ls1 += __shfl_xor_sync(0xffffffffu, ls1, 1);
        ls1 += __shfl_xor_sync(0xffffffffu, ls1, 2);
        l0 = l0 * fac0 + ls0;
        l1 = l1 * fac1 + ls1;
        m0 = mn0; m1 = mn1;

        #pragma unroll
        for (int j = 0; j < 8; j++) {
            oacc[j][0] *= fac0; oacc[j][1] *= fac0;
            oacc[j][2] *= fac1; oacc[j][3] *= fac1;
        }

        // ---- O += P V : D-frag pairs ARE the A-frag pairs (no shuffles) ----
        #pragma unroll
        for (int ks = 0; ks < 4; ks++) {
            uint32_t phi[4], plo[4];
            split_bf2(sacc[2 * ks][0],     sacc[2 * ks][1],     phi[0], plo[0]);
            split_bf2(sacc[2 * ks][2],     sacc[2 * ks][3],     phi[1], plo[1]);
            split_bf2(sacc[2 * ks + 1][0], sacc[2 * ks + 1][1], phi[2], plo[2]);
            split_bf2(sacc[2 * ks + 1][2], sacc[2 * ks + 1][3], phi[3], plo[3]);
            const uint32_t c1x = ((uint32_t)(8 * ks + lc)) ^ xmask;
            const uint32_t c2x = ((uint32_t)(8 * ks + lc + 4)) ^ xmask;
            #pragma unroll
            for (int j = 0; j < 8; j++) {
                const uint32_t nb = (uint32_t)(8 * j + lr) * 32;
                uint32_t bvh[2] = { Vhi[nb + c1x], Vhi[nb + c2x] };
                mma_bf16(oacc[j], phi, bvh);
                mma_bf16(oacc[j], plo, bvh);
                uint32_t bvl[2] = { Vlo[nb + c1x], Vlo[nb + c2x] };
                mma_bf16(oacc[j], phi, bvl);
            }
        }
    }

    // ---- Write O, normalized ----
    const float inv0 = 1.0f / l0, inv1 = 1.0f / l1;
    const int row = q0 + 16 * w + lr;
    float* ob0 = out + ((size_t)(b * SEQ + row)) * HIDDEN + h * HS;
    float* ob1 = out + ((size_t)(b * SEQ + row + 8)) * HIDDEN + h * HS;
    #pragma unroll
    for (int j = 0; j < 8; j++) {
        const int c = 8 * j + 2 * lc;
        *(float2*)(ob0 + c) = make_float2(oacc[j][0] * inv0, oacc[j][1] * inv0);
        *(float2*)(ob1 + c) = make_float2(oacc[j][2] * inv1, oacc[j][3] * inv1);
    }
}

// ---------------------------------------------------------------------------
// Launch
// ---------------------------------------------------------------------------
extern "C" void kernel_launch(void* const* d_in, const int* in_sizes, int n_in,
                              void* d_out, int out_size) {
    const float* x    = (const float*)d_in[0];
    const float* W    = (const float*)d_in[1];
    const float* bias = (const float*)d_in[2];
    float* out = (float*)d_out;

    cvt_half<<<(unsigned)((NX4 + NW4 + 255) / 256), 256>>>(x, W);

    cudaFuncSetAttribute(qkv_gemm_tc,
                         cudaFuncAttributeMaxDynamicSharedMemorySize,
                         GEMM_SMEM_BYTES);
    qkv_gemm_tc<<<dim3(N_COLS / 128, M_ROWS / 128), 256, GEMM_SMEM_BYTES>>>(bias);

    cudaFuncSetAttribute(attn_mma,
                         cudaFuncAttributeMaxDynamicSharedMemorySize,
                         ATT_SMEM_BYTES);
    attn_mma<<<dim3(SEQ / 128, N_HEADS, BATCH), 256, ATT_SMEM_BYTES>>>(out);
}

// round 13
// speedup vs baseline: 1.3105x; 1.0333x over previous
#include <cuda_runtime.h>
#include <cuda_bf16.h>
#include <cuda_fp16.h>
#include <cstdint>
#include <math.h>

#define N_HEADS 16
#define HIDDEN  1024
#define HS      64
#define BATCH   2
#define SEQ     2048
#define M_ROWS  (BATCH * SEQ)      // 4096
#define N_COLS  (3 * HIDDEN)       // 3072

// fp16 copies of the GEMM inputs (prepass output)
__device__ __half g_xh[(size_t)M_ROWS * HIDDEN];
__device__ __half g_wh[(size_t)HIDDEN * N_COLS];
// Split bf16 QKV written by the GEMM epilogue (per (b*16+h) head):
//   Q (pre-scaled x0.125) and K: [t][d];  V: [d][t]
#define HEADELEMS ((size_t)SEQ * HS)
__device__ __nv_bfloat16 g_qhi[(size_t)BATCH * N_HEADS * HEADELEMS];
__device__ __nv_bfloat16 g_qlo[(size_t)BATCH * N_HEADS * HEADELEMS];
__device__ __nv_bfloat16 g_khi[(size_t)BATCH * N_HEADS * HEADELEMS];
__device__ __nv_bfloat16 g_klo[(size_t)BATCH * N_HEADS * HEADELEMS];
__device__ __nv_bfloat16 g_vhi[(size_t)BATCH * N_HEADS * HEADELEMS];
__device__ __nv_bfloat16 g_vlo[(size_t)BATCH * N_HEADS * HEADELEMS];

// ---------------------------------------------------------------------------
// Helpers
// ---------------------------------------------------------------------------
__device__ __forceinline__ uint32_t smem_u32(const void* p) {
    uint32_t a;
    asm("{ .reg .u64 t; cvta.to.shared.u64 t, %1; cvt.u32.u64 %0, t; }"
        : "=r"(a) : "l"(p));
    return a;
}
__device__ __forceinline__ void mma_fp16(float* d, const uint32_t* a,
                                         const uint32_t* b) {
    asm volatile(
        "mma.sync.aligned.m16n8k16.row.col.f32.f16.f16.f32 "
        "{%0,%1,%2,%3}, {%4,%5,%6,%7}, {%8,%9}, {%0,%1,%2,%3};"
        : "+f"(d[0]), "+f"(d[1]), "+f"(d[2]), "+f"(d[3])
        : "r"(a[0]), "r"(a[1]), "r"(a[2]), "r"(a[3]),
          "r"(b[0]), "r"(b[1]));
}
__device__ __forceinline__ void mma_bf16(float* d, const uint32_t* a,
                                         const uint32_t* b) {
    asm volatile(
        "mma.sync.aligned.m16n8k16.row.col.f32.bf16.bf16.f32 "
        "{%0,%1,%2,%3}, {%4,%5,%6,%7}, {%8,%9}, {%0,%1,%2,%3};"
        : "+f"(d[0]), "+f"(d[1]), "+f"(d[2]), "+f"(d[3])
        : "r"(a[0]), "r"(a[1]), "r"(a[2]), "r"(a[3]),
          "r"(b[0]), "r"(b[1]));
}
__device__ __forceinline__ void ldsm_x4(uint32_t& r0, uint32_t& r1,
                                        uint32_t& r2, uint32_t& r3,
                                        uint32_t addr) {
    asm volatile("ldmatrix.sync.aligned.m8n8.x4.shared.b16 {%0,%1,%2,%3}, [%4];"
                 : "=r"(r0), "=r"(r1), "=r"(r2), "=r"(r3) : "r"(addr));
}
__device__ __forceinline__ void ldsm_x4_t(uint32_t& r0, uint32_t& r1,
                                          uint32_t& r2, uint32_t& r3,
                                          uint32_t addr) {
    asm volatile("ldmatrix.sync.aligned.m8n8.x4.trans.shared.b16 {%0,%1,%2,%3}, [%4];"
                 : "=r"(r0), "=r"(r1), "=r"(r2), "=r"(r3) : "r"(addr));
}
// Split (x,y) into bf16x2 hi and bf16x2 lo (residual). Low half = x.
__device__ __forceinline__ void split_bf2(float x, float y,
                                          uint32_t& hi, uint32_t& lo) {
    __nv_bfloat16 hx = __float2bfloat16_rn(x);
    __nv_bfloat16 hy = __float2bfloat16_rn(y);
    __nv_bfloat162 hp; hp.x = hx; hp.y = hy;
    hi = *reinterpret_cast<uint32_t*>(&hp);
    __nv_bfloat162 lp;
    lp.x = __float2bfloat16_rn(x - __bfloat162float(hx));
    lp.y = __float2bfloat16_rn(y - __bfloat162float(hy));
    lo = *reinterpret_cast<uint32_t*>(&lp);
}
__device__ __forceinline__ void cp16(uint32_t dst, const void* src) {
    asm volatile("cp.async.cg.shared.global [%0], [%1], 16;"
                 :: "r"(dst), "l"(src) : "memory");
}
#define CP_COMMIT() asm volatile("cp.async.commit_group;" ::: "memory")
#define CP_WAIT1()  asm volatile("cp.async.wait_group 1;" ::: "memory")
#define CP_WAIT0()  asm volatile("cp.async.wait_group 0;" ::: "memory")

// ---------------------------------------------------------------------------
// Kernel 0: fp32 -> fp16 prepass for x and W.
// ---------------------------------------------------------------------------
#define NX4 ((size_t)M_ROWS * HIDDEN / 4)   // 1048576
#define NW4 ((size_t)HIDDEN * N_COLS / 4)   // 786432

__global__ void __launch_bounds__(256) cvt_half(const float* __restrict__ x,
                                                const float* __restrict__ W) {
    size_t i = (size_t)blockIdx.x * 256 + threadIdx.x;
    if (i < NX4) {
        float4 v = ((const float4*)x)[i];
        __half2* dst = (__half2*)(g_xh + i * 4);
        dst[0] = __floats2half2_rn(v.x, v.y);
        dst[1] = __floats2half2_rn(v.z, v.w);
    } else if (i < NX4 + NW4) {
        size_t j = i - NX4;
        float4 v = ((const float4*)W)[j];
        __half2* dst = (__half2*)(g_wh + j * 4);
        dst[0] = __floats2half2_rn(v.x, v.y);
        dst[1] = __floats2half2_rn(v.z, v.w);
    }
}

// ---------------------------------------------------------------------------
// Kernel 1: QKV GEMM via mma.sync fp16 m16n8k16 with ldmatrix fragments
// (R12 structure). Epilogue: bias + reshape scatter, writing SPLIT bf16:
//   Q third: scaled x0.125, split -> g_qhi/g_qlo [t][d]
//   K third: split -> g_khi/g_klo [t][d]
//   V third: split -> g_vhi/g_vlo [d][t]
// Reshape algebra: g = 3r + c/1024; e = c%1024; u=g>>11; t=g&2047;
// h=e&15; d=e>>4.
// ---------------------------------------------------------------------------
#define GBK   32
#define GNIT  (HIDDEN / GBK)          // 32
#define CSTR  132
#define AST_B 10240                   // A stage bytes (128 * 80)
#define STG_B 18432                   // A (10240) + B (8192)
#define GEMM_SMEM_BYTES (CSTR * 128 * 4)   // 67584 >= 2*18432

__global__ void __launch_bounds__(256, 2) qkv_gemm_tc(const float* __restrict__ bias)
{
    extern __shared__ char smc[];
    const uint32_t sbase = smem_u32(smc);
    const int tid  = threadIdx.x;
    const int lane = tid & 31;
    const int wid  = tid >> 5;
    const int wm   = wid & 1;
    const int wn   = wid >> 1;
    const int m0 = blockIdx.y * 128, n0 = blockIdx.x * 128;
    const int lr = lane >> 2, lc = lane & 3;

    uint32_t a_dst[2], b_dst[2];
    const __half* a_src[2];
    const __half* b_src[2];
    #pragma unroll
    for (int i = 0; i < 2; i++) {
        int id = tid + i * 256;
        int am = id >> 2, ac = id & 3;
        a_dst[i] = (uint32_t)(am * 80 + ac * 16);
        a_src[i] = g_xh + (size_t)(m0 + am) * HIDDEN + ac * 8;
        int bk = id >> 4, bc = id & 15;
        b_dst[i] = (uint32_t)(AST_B + bk * 256 + ((bc * 16) ^ ((bk & 7) << 4)));
        b_src[i] = g_wh + (size_t)bk * N_COLS + n0 + bc * 8;
    }

    const int g = lane >> 3, r = lane & 7;
    const uint32_t a_lane = (uint32_t)((wm * 64 + ((g & 1) << 3) + r) * 80
                                       + (((g >> 1) << 3) << 1));
    const uint32_t b_rowb  = (uint32_t)((((g & 1) << 3) + r) * 256);
    const uint32_t b_colh0 = (uint32_t)(wn * 32 + ((g >> 1) << 3));
    const uint32_t b_xor   = (uint32_t)(r << 4);

    float acc[4][4][4] = {};

    #pragma unroll
    for (int i = 0; i < 2; i++) {
        cp16(sbase + a_dst[i], a_src[i]);
        cp16(sbase + b_dst[i], b_src[i]);
    }
    CP_COMMIT();

    for (int it = 0; it < GNIT; ++it) {
        const uint32_t buf = (uint32_t)(it & 1) * STG_B;
        if (it + 1 < GNIT) {
            const uint32_t nb = (uint32_t)((it + 1) & 1) * STG_B;
            #pragma unroll
            for (int i = 0; i < 2; i++) {
                cp16(sbase + nb + a_dst[i], a_src[i] + (it + 1) * GBK);
                cp16(sbase + nb + b_dst[i], b_src[i] + (size_t)(it + 1) * GBK * N_COLS);
            }
            CP_COMMIT();
            CP_WAIT1();
        } else {
            CP_WAIT0();
        }
        __syncthreads();

        #pragma unroll
        for (int ks = 0; ks < 2; ks++) {
            uint32_t bf[4][2];
            #pragma unroll
            for (int nblk = 0; nblk < 2; nblk++) {
                uint32_t baddr = sbase + buf + AST_B + b_rowb + (uint32_t)(ks * 4096)
                               + ((((b_colh0 + nblk * 16) << 1)) ^ b_xor);
                uint32_t r0, r1, r2, r3;
                ldsm_x4_t(r0, r1, r2, r3, baddr);
                bf[nblk * 2 + 0][0] = r0; bf[nblk * 2 + 0][1] = r1;
                bf[nblk * 2 + 1][0] = r2; bf[nblk * 2 + 1][1] = r3;
            }
            #pragma unroll
            for (int mf = 0; mf < 4; mf++) {
                uint32_t af[4];
                ldsm_x4(af[0], af[1], af[2], af[3],
                        sbase + buf + a_lane + mf * 1280 + ks * 32);
                #pragma unroll
                for (int nf = 0; nf < 4; nf++)
                    mma_fp16(acc[mf][nf], af, bf[nf]);
            }
        }
        __syncthreads();
    }

    // ---- Epilogue via smem ----
    float* Cs = (float*)smc;
    #pragma unroll
    for (int mf = 0; mf < 4; mf++) {
        const int rr = wm * 64 + mf * 16 + lr;
        #pragma unroll
        for (int nf = 0; nf < 4; nf++) {
            const int c = wn * 32 + nf * 8 + 2 * lc;
            *(float2*)&Cs[rr * CSTR + c]       = make_float2(acc[mf][nf][0], acc[mf][nf][1]);
            *(float2*)&Cs[(rr + 8) * CSTR + c] = make_float2(acc[mf][nf][2], acc[mf][nf][3]);
        }
    }
    __syncthreads();

    {
        const int rr = tid >> 1;
        const int half = tid & 1;
        const int rglob = m0 + rr;
        const int gg = 3 * rglob + (n0 >> 10);
        const int u = gg >> 11, t = gg & 2047;
        const int d0 = (n0 & 1023) >> 4;
        const int kind = u >> 1;            // 0=Q, 1=K, 2=V
        const int bb = u & 1;               // batch
        #pragma unroll
        for (int j = 0; j < 8; j++) {
            const int hh = half * 8 + j;
            float o[8];
            #pragma unroll
            for (int e = 0; e < 8; e++)
                o[e] = Cs[rr * CSTR + hh + 16 * e] + __ldg(&bias[n0 + hh + 16 * e]);
            const size_t head = (size_t)(bb * 16 + hh) * HEADELEMS;
            if (kind == 2) {
                // V: [d][t], scalar split stores
                #pragma unroll
                for (int e = 0; e < 8; e++) {
                    __nv_bfloat16 hv = __float2bfloat16_rn(o[e]);
                    __nv_bfloat16 lv = __float2bfloat16_rn(o[e] - __bfloat162float(hv));
                    size_t off = head + (size_t)(d0 + e) * SEQ + t;
                    g_vhi[off] = hv;
                    g_vlo[off] = lv;
                }
            } else {
                uint32_t hi[4], lo[4];
                if (kind == 0) {
                    #pragma unroll
                    for (int p = 0; p < 4; p++)
                        split_bf2(o[2 * p] * 0.125f, o[2 * p + 1] * 0.125f, hi[p], lo[p]);
                } else {
                    #pragma unroll
                    for (int p = 0; p < 4; p++)
                        split_bf2(o[2 * p], o[2 * p + 1], hi[p], lo[p]);
                }
                size_t off = head + (size_t)t * HS + d0;
                __nv_bfloat16* dh = (kind == 0) ? g_qhi : g_khi;
                __nv_bfloat16* dl = (kind == 0) ? g_qlo : g_klo;
                *(uint4*)(dh + off) = make_uint4(hi[0], hi[1], hi[2], hi[3]);
                *(uint4*)(dl + off) = make_uint4(lo[0], lo[1], lo[2], lo[3]);
            }
        }
    }
}

// ---------------------------------------------------------------------------
// Kernel 2: flash attention via mma.sync bf16 m16n8k16, split-2 precision.
// Pre-split bf16 Q/K/V loaded by cp.async (no per-tile LDG/split/STS).
// SMEM (uint32): Qhi 0, Qlo 4096; K/V double buffers at 8192 + buf*8192:
//   Khi +0, Klo +2048, Vhi +4096, Vlo +6144.  Total 24576 u32 = 96KB.
// ---------------------------------------------------------------------------
#define ATT_SMEM_BYTES (24576 * 4)
#define KVB 8192          // u32 offset of KV buffers
#define KVSTRIDE 8192     // u32 stride between buffers

__global__ void __launch_bounds__(256, 2) attn_mma(float* __restrict__ out) {
    extern __shared__ uint32_t sm[];
    const uint32_t sb = smem_u32(sm);
    uint32_t* Qhi = sm;
    uint32_t* Qlo = sm + 4096;

    const int tid  = threadIdx.x;
    const int lane = tid & 31;
    const int w    = tid >> 5;          // warp 0..7, rows [16w,16w+16)
    const int lr   = lane >> 2, lc = lane & 3;
    const int qtile = (int)(gridDim.x - 1) - (int)blockIdx.x;  // long CTAs first
    const int h = blockIdx.y, b = blockIdx.z;
    const int q0 = qtile * 128;

    const size_t head = (size_t)(b * 16 + h) * HEADELEMS;
    const __nv_bfloat16* qhg = g_qhi + head;
    const __nv_bfloat16* qlg = g_qlo + head;
    const __nv_bfloat16* khg = g_khi + head;
    const __nv_bfloat16* klg = g_klo + head;
    const __nv_bfloat16* vhg = g_vhi + head;
    const __nv_bfloat16* vlg = g_vlo + head;

    // Per-thread KV chunk mapping (2 chunks of 16B per array)
    uint32_t kv_dst[2];         // byte offset within one array region
    int      kv_row[2], kv_c[2];
    #pragma unroll
    for (int i = 0; i < 2; i++) {
        int id = tid + i * 256;
        kv_row[i] = id >> 3;
        kv_c[i]   = id & 7;
        kv_dst[i] = (uint32_t)((kv_row[i] * 32 + ((kv_c[i] ^ (kv_row[i] & 7)) << 2)) * 4);
    }

    // ---- Prologue: Q (group with KV0) ----
    #pragma unroll
    for (int i = 0; i < 4; i++) {
        int id = tid + i * 256;
        int rq = id >> 3, cq = id & 7;
        uint32_t d = (uint32_t)((rq * 32 + ((cq ^ (rq & 7)) << 2)) * 4);
        cp16(sb + d,         qhg + (size_t)(q0 + rq) * HS + cq * 8);
        cp16(sb + 16384 + d, qlg + (size_t)(q0 + rq) * HS + cq * 8);
    }
    #pragma unroll
    for (int i = 0; i < 2; i++) {
        uint32_t base = sb + KVB * 4;
        cp16(base + kv_dst[i],         khg + (size_t)kv_row[i] * HS + kv_c[i] * 8);
        cp16(base + 8192  + kv_dst[i], klg + (size_t)kv_row[i] * HS + kv_c[i] * 8);
        cp16(base + 16384 + kv_dst[i], vhg + (size_t)kv_row[i] * SEQ + kv_c[i] * 8);
        cp16(base + 24576 + kv_dst[i], vlg + (size_t)kv_row[i] * SEQ + kv_c[i] * 8);
    }
    CP_COMMIT();

    float oacc[8][4];
    #pragma unroll
    for (int j = 0; j < 8; j++)
        #pragma unroll
        for (int k = 0; k < 4; k++) oacc[j][k] = 0.0f;
    float m0 = -1e30f, m1 = -1e30f, l0 = 0.0f, l1 = 0.0f;

    const uint32_t xmask = (uint32_t)lr << 2;

    const int nkt = 2 * qtile + 2;
    for (int kt = 0; kt < nkt; kt++) {
        const int k0g = kt * 64;
        if (kt + 1 < nkt) {
            const int k0n = (kt + 1) * 64;
            const uint32_t base = sb + (KVB + ((kt + 1) & 1) * KVSTRIDE) * 4;
            #pragma unroll
            for (int i = 0; i < 2; i++) {
                cp16(base + kv_dst[i],         khg + (size_t)(k0n + kv_row[i]) * HS + kv_c[i] * 8);
                cp16(base + 8192  + kv_dst[i], klg + (size_t)(k0n + kv_row[i]) * HS + kv_c[i] * 8);
                cp16(base + 16384 + kv_dst[i], vhg + (size_t)kv_row[i] * SEQ + k0n + kv_c[i] * 8);
                cp16(base + 24576 + kv_dst[i], vlg + (size_t)kv_row[i] * SEQ + k0n + kv_c[i] * 8);
            }
            CP_COMMIT();
            CP_WAIT1();
        } else {
            CP_WAIT0();
        }
        __syncthreads();   // tile kt visible to all

        if (k0g <= q0 + 16 * w + 15) {
            const uint32_t* Khi = sm + KVB + (kt & 1) * KVSTRIDE;
            const uint32_t* Klo = Khi + 2048;
            const uint32_t* Vhi = Khi + 4096;
            const uint32_t* Vlo = Khi + 6144;

            // ---- S = Q K^T (bf16 split-2, 3-term) ----
            float sacc[8][4];
            #pragma unroll
            for (int j = 0; j < 8; j++)
                #pragma unroll
                for (int k = 0; k < 4; k++) sacc[j][k] = 0.0f;

            const int r = 16 * w + lr;
            const uint32_t qbase = r * 32;
            #pragma unroll
            for (int ks = 0; ks < 4; ks++) {
                const uint32_t c1x = ((uint32_t)(8 * ks + lc)) ^ xmask;
                const uint32_t c2x = ((uint32_t)(8 * ks + lc + 4)) ^ xmask;
                uint32_t ahi[4], alo[4];
                ahi[0] = Qhi[qbase + c1x];       alo[0] = Qlo[qbase + c1x];
                ahi[1] = Qhi[qbase + 256 + c1x]; alo[1] = Qlo[qbase + 256 + c1x];
                ahi[2] = Qhi[qbase + c2x];       alo[2] = Qlo[qbase + c2x];
                ahi[3] = Qhi[qbase + 256 + c2x]; alo[3] = Qlo[qbase + 256 + c2x];
                #pragma unroll
                for (int j = 0; j < 8; j++) {
                    const uint32_t nb = (uint32_t)(8 * j + lr) * 32;
                    uint32_t bh[2] = { Khi[nb + c1x], Khi[nb + c2x] };
                    mma_bf16(sacc[j], ahi, bh);
                    mma_bf16(sacc[j], alo, bh);
                    uint32_t bl[2] = { Klo[nb + c1x], Klo[nb + c2x] };
                    mma_bf16(sacc[j], ahi, bl);
                }
            }

            // ---- Causal mask (only near diagonal) ----
            const int row0 = q0 + 16 * w + lr;
            if (k0g + 63 > q0 + 16 * w) {
                #pragma unroll
                for (int j = 0; j < 8; j++) {
                    const int c0 = k0g + 8 * j + 2 * lc;
                    if (c0 > row0)         sacc[j][0] = -1e30f;
                    if (c0 + 1 > row0)     sacc[j][1] = -1e30f;
                    if (c0 > row0 + 8)     sacc[j][2] = -1e30f;
                    if (c0 + 1 > row0 + 8) sacc[j][3] = -1e30f;
                }
            }

            // ---- Online softmax ----
            float ml0 = -1e30f, ml1 = -1e30f;
            #pragma unroll
            for (int j = 0; j < 8; j++) {
                ml0 = fmaxf(ml0, fmaxf(sacc[j][0], sacc[j][1]));
                ml1 = fmaxf(ml1, fmaxf(sacc[j][2], sacc[j][3]));
            }
            ml0 = fmaxf(ml0, __shfl_xor_sync(0xffffffffu, ml0, 1));
            ml0 = fmaxf(ml0, __shfl_xor_sync(0xffffffffu, ml0, 2));
            ml1 = fmaxf(ml1, __shfl_xor_sync(0xffffffffu, ml1, 1));
            ml1 = fmaxf(ml1, __shfl_xor_sync(0xffffffffu, ml1, 2));

            const float mn0 = fmaxf(m0, ml0), mn1 = fmaxf(m1, ml1);
            const float fac0 = __expf(m0 - mn0), fac1 = __expf(m1 - mn1);
            float ls0 = 0.0f, ls1 = 0.0f;
            #pragma unroll
            for (int j = 0; j < 8; j++) {
                float p0 = __expf(sacc[j][0] - mn0);
                float p1 = __expf(sacc[j][1] - mn0);
                float p2 = __expf(sacc[j][2] - mn1);
                float p3 = __expf(sacc[j][3] - mn1);
                sacc[j][0] = p0; sacc[j][1] = p1; sacc[j][2] = p2; sacc[j][3] = p3;
                ls0 += p0 + p1; ls1 += p2 + p3;
            }
            ls0 += __shfl_xor_sync(0xffffffffu, ls0, 1);
            ls0 += __shfl_xor_sync(0xffffffffu, ls0, 2);
            ls1 += __shfl_xor_sync(0xffffffffu, ls1, 1);
            ls1 += __shfl_xor_sync(0xffffffffu, ls1, 2);
            l0 = l0 * fac0 + ls0;
            l1 = l1 * fac1 + ls1;
            m0 = mn0; m1 = mn1;

            #pragma unroll
            for (int j = 0; j < 8; j++) {
                oacc[j][0] *= fac0; oacc[j][1] *= fac0;
                oacc[j][2] *= fac1; oacc[j][3] *= fac1;
            }

            // ---- O += P V : D-frag pairs ARE the A-frag pairs ----
            #pragma unroll
            for (int ks = 0; ks < 4; ks++) {
                uint32_t phi[4], plo[4];
                split_bf2(sacc[2 * ks][0],     sacc[2 * ks][1],     phi[0], plo[0]);
                split_bf2(sacc[2 * ks][2],     sacc[2 * ks][3],     phi[1], plo[1]);
                split_bf2(sacc[2 * ks + 1][0], sacc[2 * ks + 1][1], phi[2], plo[2]);
                split_bf2(sacc[2 * ks + 1][2], sacc[2 * ks + 1][3], phi[3], plo[3]);
                const uint32_t c1x = ((uint32_t)(8 * ks + lc)) ^ xmask;
                const uint32_t c2x = ((uint32_t)(8 * ks + lc + 4)) ^ xmask;
                #pragma unroll
                for (int j = 0; j < 8; j++) {
                    const uint32_t nb = (uint32_t)(8 * j + lr) * 32;
                    uint32_t bvh[2] = { Vhi[nb + c1x], Vhi[nb + c2x] };
                    mma_bf16(oacc[j], phi, bvh);
                    mma_bf16(oacc[j], plo, bvh);
                    uint32_t bvl[2] = { Vlo[nb + c1x], Vlo[nb + c2x] };
                    mma_bf16(oacc[j], phi, bvl);
                }
            }
        }
        __syncthreads();   // consumers done; buffer free for reuse
    }

    // ---- Write O, normalized ----
    const float inv0 = 1.0f / l0, inv1 = 1.0f / l1;
    const int row = q0 + 16 * w + lr;
    float* ob0 = out + ((size_t)(b * SEQ + row)) * HIDDEN + h * HS;
    float* ob1 = out + ((size_t)(b * SEQ + row + 8)) * HIDDEN + h * HS;
    #pragma unroll
    for (int j = 0; j < 8; j++) {
        const int c = 8 * j + 2 * lc;
        *(float2*)(ob0 + c) = make_float2(oacc[j][0] * inv0, oacc[j][1] * inv0);
        *(float2*)(ob1 + c) = make_float2(oacc[j][2] * inv1, oacc[j][3] * inv1);
    }
}

// ---------------------------------------------------------------------------
// Launch
// ---------------------------------------------------------------------------
extern "C" void kernel_launch(void* const* d_in, const int* in_sizes, int n_in,
                              void* d_out, int out_size) {
    const float* x    = (const float*)d_in[0];
    const float* W    = (const float*)d_in[1];
    const float* bias = (const float*)d_in[2];
    float* out = (float*)d_out;

    cvt_half<<<(unsigned)((NX4 + NW4 + 255) / 256), 256>>>(x, W);

    cudaFuncSetAttribute(qkv_gemm_tc,
                         cudaFuncAttributeMaxDynamicSharedMemorySize,
                         GEMM_SMEM_BYTES);
    qkv_gemm_tc<<<dim3(N_COLS / 128, M_ROWS / 128), 256, GEMM_SMEM_BYTES>>>(bias);

    cudaFuncSetAttribute(attn_mma,
                         cudaFuncAttributeMaxDynamicSharedMemorySize,
                         ATT_SMEM_BYTES);
    attn_mma<<<dim3(SEQ / 128, N_HEADS, BATCH), 256, ATT_SMEM_BYTES>>>(out);
}

// round 14
// speedup vs baseline: 1.6579x; 1.2651x over previous
#include <cuda_runtime.h>
#include <cuda_bf16.h>
#include <cuda_fp16.h>
#include <cstdint>
#include <math.h>

#define N_HEADS 16
#define HIDDEN  1024
#define HS      64
#define BATCH   2
#define SEQ     2048
#define M_ROWS  (BATCH * SEQ)      // 4096
#define N_COLS  (3 * HIDDEN)       // 3072

// fp16 copies of the GEMM inputs (prepass output)
__device__ __half g_xh[(size_t)M_ROWS * HIDDEN];
__device__ __half g_wh[(size_t)HIDDEN * N_COLS];
// Attention operands written by the GEMM epilogue (per (b*16+h) head):
//   Q: pre-scaled x0.125, SPLIT fp16 hi/lo, [t][d]
//   K: single fp16, [t][d]
//   V: single fp16, [d][t]
#define HEADELEMS ((size_t)SEQ * HS)
__device__ __half g_qhi[(size_t)BATCH * N_HEADS * HEADELEMS];
__device__ __half g_qlo[(size_t)BATCH * N_HEADS * HEADELEMS];
__device__ __half g_kh [(size_t)BATCH * N_HEADS * HEADELEMS];
__device__ __half g_vh [(size_t)BATCH * N_HEADS * HEADELEMS];

// ---------------------------------------------------------------------------
// Helpers
// ---------------------------------------------------------------------------
__device__ __forceinline__ uint32_t smem_u32(const void* p) {
    uint32_t a;
    asm("{ .reg .u64 t; cvta.to.shared.u64 t, %1; cvt.u32.u64 %0, t; }"
        : "=r"(a) : "l"(p));
    return a;
}
__device__ __forceinline__ void mma_fp16(float* d, const uint32_t* a,
                                         const uint32_t* b) {
    asm volatile(
        "mma.sync.aligned.m16n8k16.row.col.f32.f16.f16.f32 "
        "{%0,%1,%2,%3}, {%4,%5,%6,%7}, {%8,%9}, {%0,%1,%2,%3};"
        : "+f"(d[0]), "+f"(d[1]), "+f"(d[2]), "+f"(d[3])
        : "r"(a[0]), "r"(a[1]), "r"(a[2]), "r"(a[3]),
          "r"(b[0]), "r"(b[1]));
}
__device__ __forceinline__ void ldsm_x4(uint32_t& r0, uint32_t& r1,
                                        uint32_t& r2, uint32_t& r3,
                                        uint32_t addr) {
    asm volatile("ldmatrix.sync.aligned.m8n8.x4.shared.b16 {%0,%1,%2,%3}, [%4];"
                 : "=r"(r0), "=r"(r1), "=r"(r2), "=r"(r3) : "r"(addr));
}
__device__ __forceinline__ void ldsm_x4_t(uint32_t& r0, uint32_t& r1,
                                          uint32_t& r2, uint32_t& r3,
                                          uint32_t addr) {
    asm volatile("ldmatrix.sync.aligned.m8n8.x4.trans.shared.b16 {%0,%1,%2,%3}, [%4];"
                 : "=r"(r0), "=r"(r1), "=r"(r2), "=r"(r3) : "r"(addr));
}
__device__ __forceinline__ uint32_t pack_h2(float x, float y) {
    __half2 h = __floats2half2_rn(x, y);
    return *reinterpret_cast<uint32_t*>(&h);
}
// Split (x,y) into fp16x2 hi and fp16x2 lo (residual).
__device__ __forceinline__ void split_h2(float x, float y,
                                         uint32_t& hi, uint32_t& lo) {
    __half2 h = __floats2half2_rn(x, y);
    hi = *reinterpret_cast<uint32_t*>(&h);
    __half2 l = __floats2half2_rn(x - __half2float(__low2half(h)),
                                  y - __half2float(__high2half(h)));
    lo = *reinterpret_cast<uint32_t*>(&l);
}
__device__ __forceinline__ void cp16(uint32_t dst, const void* src) {
    asm volatile("cp.async.cg.shared.global [%0], [%1], 16;"
                 :: "r"(dst), "l"(src) : "memory");
}
#define CP_COMMIT() asm volatile("cp.async.commit_group;" ::: "memory")
#define CP_WAIT1()  asm volatile("cp.async.wait_group 1;" ::: "memory")
#define CP_WAIT0()  asm volatile("cp.async.wait_group 0;" ::: "memory")

// ---------------------------------------------------------------------------
// Kernel 0: fp32 -> fp16 prepass for x and W.
// ---------------------------------------------------------------------------
#define NX4 ((size_t)M_ROWS * HIDDEN / 4)   // 1048576
#define NW4 ((size_t)HIDDEN * N_COLS / 4)   // 786432

__global__ void __launch_bounds__(256) cvt_half(const float* __restrict__ x,
                                                const float* __restrict__ W) {
    size_t i = (size_t)blockIdx.x * 256 + threadIdx.x;
    if (i < NX4) {
        float4 v = ((const float4*)x)[i];
        __half2* dst = (__half2*)(g_xh + i * 4);
        dst[0] = __floats2half2_rn(v.x, v.y);
        dst[1] = __floats2half2_rn(v.z, v.w);
    } else if (i < NX4 + NW4) {
        size_t j = i - NX4;
        float4 v = ((const float4*)W)[j];
        __half2* dst = (__half2*)(g_wh + j * 4);
        dst[0] = __floats2half2_rn(v.x, v.y);
        dst[1] = __floats2half2_rn(v.z, v.w);
    }
}

// ---------------------------------------------------------------------------
// Kernel 1: QKV GEMM via mma.sync fp16 m16n8k16 with ldmatrix fragments
// (R12/R13 structure, ~110us). Epilogue: bias + reshape scatter:
//   Q third: scaled x0.125, split fp16 -> g_qhi/g_qlo [t][d]
//   K third: single fp16 -> g_kh [t][d]
//   V third: single fp16 -> g_vh [d][t]
// Reshape algebra: g = 3r + c/1024; e = c%1024; u=g>>11; t=g&2047;
// h=e&15; d=e>>4.
// ---------------------------------------------------------------------------
#define GBK   32
#define GNIT  (HIDDEN / GBK)          // 32
#define CSTR  132
#define AST_B 10240                   // A stage bytes (128 * 80)
#define STG_B 18432                   // A (10240) + B (8192)
#define GEMM_SMEM_BYTES (CSTR * 128 * 4)   // 67584 >= 2*18432

__global__ void __launch_bounds__(256, 2) qkv_gemm_tc(const float* __restrict__ bias)
{
    extern __shared__ char smc[];
    const uint32_t sbase = smem_u32(smc);
    const int tid  = threadIdx.x;
    const int lane = tid & 31;
    const int wid  = tid >> 5;
    const int wm   = wid & 1;
    const int wn   = wid >> 1;
    const int m0 = blockIdx.y * 128, n0 = blockIdx.x * 128;
    const int lr = lane >> 2, lc = lane & 3;

    uint32_t a_dst[2], b_dst[2];
    const __half* a_src[2];
    const __half* b_src[2];
    #pragma unroll
    for (int i = 0; i < 2; i++) {
        int id = tid + i * 256;
        int am = id >> 2, ac = id & 3;
        a_dst[i] = (uint32_t)(am * 80 + ac * 16);
        a_src[i] = g_xh + (size_t)(m0 + am) * HIDDEN + ac * 8;
        int bk = id >> 4, bc = id & 15;
        b_dst[i] = (uint32_t)(AST_B + bk * 256 + ((bc * 16) ^ ((bk & 7) << 4)));
        b_src[i] = g_wh + (size_t)bk * N_COLS + n0 + bc * 8;
    }

    const int g = lane >> 3, r = lane & 7;
    const uint32_t a_lane = (uint32_t)((wm * 64 + ((g & 1) << 3) + r) * 80
                                       + (((g >> 1) << 3) << 1));
    const uint32_t b_rowb  = (uint32_t)((((g & 1) << 3) + r) * 256);
    const uint32_t b_colh0 = (uint32_t)(wn * 32 + ((g >> 1) << 3));
    const uint32_t b_xor   = (uint32_t)(r << 4);

    float acc[4][4][4] = {};

    #pragma unroll
    for (int i = 0; i < 2; i++) {
        cp16(sbase + a_dst[i], a_src[i]);
        cp16(sbase + b_dst[i], b_src[i]);
    }
    CP_COMMIT();

    for (int it = 0; it < GNIT; ++it) {
        const uint32_t buf = (uint32_t)(it & 1) * STG_B;
        if (it + 1 < GNIT) {
            const uint32_t nb = (uint32_t)((it + 1) & 1) * STG_B;
            #pragma unroll
            for (int i = 0; i < 2; i++) {
                cp16(sbase + nb + a_dst[i], a_src[i] + (it + 1) * GBK);
                cp16(sbase + nb + b_dst[i], b_src[i] + (size_t)(it + 1) * GBK * N_COLS);
            }
            CP_COMMIT();
            CP_WAIT1();
        } else {
            CP_WAIT0();
        }
        __syncthreads();

        #pragma unroll
        for (int ks = 0; ks < 2; ks++) {
            uint32_t bf[4][2];
            #pragma unroll
            for (int nblk = 0; nblk < 2; nblk++) {
                uint32_t baddr = sbase + buf + AST_B + b_rowb + (uint32_t)(ks * 4096)
                               + ((((b_colh0 + nblk * 16) << 1)) ^ b_xor);
                uint32_t r0, r1, r2, r3;
                ldsm_x4_t(r0, r1, r2, r3, baddr);
                bf[nblk * 2 + 0][0] = r0; bf[nblk * 2 + 0][1] = r1;
                bf[nblk * 2 + 1][0] = r2; bf[nblk * 2 + 1][1] = r3;
            }
            #pragma unroll
            for (int mf = 0; mf < 4; mf++) {
                uint32_t af[4];
                ldsm_x4(af[0], af[1], af[2], af[3],
                        sbase + buf + a_lane + mf * 1280 + ks * 32);
                #pragma unroll
                for (int nf = 0; nf < 4; nf++)
                    mma_fp16(acc[mf][nf], af, bf[nf]);
            }
        }
        __syncthreads();
    }

    // ---- Epilogue via smem ----
    float* Cs = (float*)smc;
    #pragma unroll
    for (int mf = 0; mf < 4; mf++) {
        const int rr = wm * 64 + mf * 16 + lr;
        #pragma unroll
        for (int nf = 0; nf < 4; nf++) {
            const int c = wn * 32 + nf * 8 + 2 * lc;
            *(float2*)&Cs[rr * CSTR + c]       = make_float2(acc[mf][nf][0], acc[mf][nf][1]);
            *(float2*)&Cs[(rr + 8) * CSTR + c] = make_float2(acc[mf][nf][2], acc[mf][nf][3]);
        }
    }
    __syncthreads();

    {
        const int rr = tid >> 1;
        const int half = tid & 1;
        const int rglob = m0 + rr;
        const int gg = 3 * rglob + (n0 >> 10);
        const int u = gg >> 11, t = gg & 2047;
        const int d0 = (n0 & 1023) >> 4;
        const int kind = u >> 1;            // 0=Q, 1=K, 2=V
        const int bb = u & 1;               // batch
        #pragma unroll
        for (int j = 0; j < 8; j++) {
            const int hh = half * 8 + j;
            float o[8];
            #pragma unroll
            for (int e = 0; e < 8; e++)
                o[e] = Cs[rr * CSTR + hh + 16 * e] + __ldg(&bias[n0 + hh + 16 * e]);
            const size_t head = (size_t)(bb * 16 + hh) * HEADELEMS;
            if (kind == 2) {
                // V: single fp16, [d][t]
                #pragma unroll
                for (int e = 0; e < 8; e++)
                    g_vh[head + (size_t)(d0 + e) * SEQ + t] = __float2half_rn(o[e]);
            } else if (kind == 1) {
                // K: single fp16, [t][d]
                uint32_t kk[4];
                #pragma unroll
                for (int p = 0; p < 4; p++)
                    kk[p] = pack_h2(o[2 * p], o[2 * p + 1]);
                *(uint4*)(g_kh + head + (size_t)t * HS + d0) =
                    make_uint4(kk[0], kk[1], kk[2], kk[3]);
            } else {
                // Q: scaled, split fp16, [t][d]
                uint32_t hi[4], lo[4];
                #pragma unroll
                for (int p = 0; p < 4; p++)
                    split_h2(o[2 * p] * 0.125f, o[2 * p + 1] * 0.125f, hi[p], lo[p]);
                size_t off = head + (size_t)t * HS + d0;
                *(uint4*)(g_qhi + off) = make_uint4(hi[0], hi[1], hi[2], hi[3]);
                *(uint4*)(g_qlo + off) = make_uint4(lo[0], lo[1], lo[2], lo[3]);
            }
        }
    }
}

// ---------------------------------------------------------------------------
// Kernel 2: flash attention via mma.sync fp16 m16n8k16.
// Q split-2 fp16 (hi/lo), K and V single fp16: QK = 2 mma, PV = 2 mma
// (P split in registers). 128 mma/warp-tile (was 192).
// SMEM (u32): Qhi 0..4095, Qlo 4096..8191; KV double buffers at
// 8192 + buf*4096: K +0 (2048), V +2048 (2048). Total 16384 u32 = 64KB.
// ---------------------------------------------------------------------------
#define ATT_SMEM_BYTES (16384 * 4)

__global__ void __launch_bounds__(256, 2) attn_mma(float* __restrict__ out) {
    extern __shared__ uint32_t sm[];
    const uint32_t sb = smem_u32(sm);
    uint32_t* Qhi = sm;
    uint32_t* Qlo = sm + 4096;

    const int tid  = threadIdx.x;
    const int lane = tid & 31;
    const int w    = tid >> 5;          // warp 0..7, rows [16w,16w+16)
    const int lr   = lane >> 2, lc = lane & 3;
    const int qtile = (int)(gridDim.x - 1) - (int)blockIdx.x;  // long CTAs first
    const int h = blockIdx.y, b = blockIdx.z;
    const int q0 = qtile * 128;

    const size_t head = (size_t)(b * 16 + h) * HEADELEMS;
    const __half* qhg = g_qhi + head;
    const __half* qlg = g_qlo + head;
    const __half* khg = g_kh + head;
    const __half* vhg = g_vh + head;

    // Per-thread KV chunk mapping (2 chunks of 16B per array per tile)
    uint32_t kv_dst[2];
    int      kv_row[2], kv_c[2];
    #pragma unroll
    for (int i = 0; i < 2; i++) {
        int id = tid + i * 256;
        kv_row[i] = id >> 3;            // 0..63
        kv_c[i]   = id & 7;
        kv_dst[i] = (uint32_t)((kv_row[i] * 32 + ((kv_c[i] ^ (kv_row[i] & 7)) << 2)) * 4);
    }

    // ---- Prologue: Q hi/lo + KV tile 0 (one group) ----
    #pragma unroll
    for (int i = 0; i < 4; i++) {
        int id = tid + i * 256;
        int rq = id >> 3, cq = id & 7;
        uint32_t d = (uint32_t)((rq * 32 + ((cq ^ (rq & 7)) << 2)) * 4);
        cp16(sb + d,         qhg + (size_t)(q0 + rq) * HS + cq * 8);
        cp16(sb + 16384 + d, qlg + (size_t)(q0 + rq) * HS + cq * 8);
    }
    #pragma unroll
    for (int i = 0; i < 2; i++) {
        uint32_t base = sb + 8192 * 4;
        cp16(base + kv_dst[i],        khg + (size_t)kv_row[i] * HS + kv_c[i] * 8);
        cp16(base + 8192 + kv_dst[i], vhg + (size_t)kv_row[i] * SEQ + kv_c[i] * 8);
    }
    CP_COMMIT();

    float oacc[8][4];
    #pragma unroll
    for (int j = 0; j < 8; j++)
        #pragma unroll
        for (int k = 0; k < 4; k++) oacc[j][k] = 0.0f;
    float m0 = -1e30f, m1 = -1e30f, l0 = 0.0f, l1 = 0.0f;

    const uint32_t xmask = (uint32_t)lr << 2;

    const int nkt = 2 * qtile + 2;
    for (int kt = 0; kt < nkt; kt++) {
        const int k0g = kt * 64;
        if (kt + 1 < nkt) {
            const int k0n = (kt + 1) * 64;
            const uint32_t base = sb + (8192 + ((kt + 1) & 1) * 4096) * 4;
            #pragma unroll
            for (int i = 0; i < 2; i++) {
                cp16(base + kv_dst[i],        khg + (size_t)(k0n + kv_row[i]) * HS + kv_c[i] * 8);
                cp16(base + 8192 + kv_dst[i], vhg + (size_t)kv_row[i] * SEQ + k0n + kv_c[i] * 8);
            }
            CP_COMMIT();
            CP_WAIT1();
        } else {
            CP_WAIT0();
        }
        __syncthreads();   // tile kt visible to all

        if (k0g <= q0 + 16 * w + 15) {
            const uint32_t* Kb = sm + 8192 + (kt & 1) * 4096;
            const uint32_t* Vb = Kb + 2048;

            // ---- S = Q K^T (Q split-2 fp16, K single: 2 mma) ----
            float sacc[8][4];
            #pragma unroll
            for (int j = 0; j < 8; j++)
                #pragma unroll
                for (int k = 0; k < 4; k++) sacc[j][k] = 0.0f;

            const int r = 16 * w + lr;
            const uint32_t qbase = r * 32;
            #pragma unroll
            for (int ks = 0; ks < 4; ks++) {
                const uint32_t c1x = ((uint32_t)(8 * ks + lc)) ^ xmask;
                const uint32_t c2x = ((uint32_t)(8 * ks + lc + 4)) ^ xmask;
                uint32_t ahi[4], alo[4];
                ahi[0] = Qhi[qbase + c1x];       alo[0] = Qlo[qbase + c1x];
                ahi[1] = Qhi[qbase + 256 + c1x]; alo[1] = Qlo[qbase + 256 + c1x];
                ahi[2] = Qhi[qbase + c2x];       alo[2] = Qlo[qbase + c2x];
                ahi[3] = Qhi[qbase + 256 + c2x]; alo[3] = Qlo[qbase + 256 + c2x];
                #pragma unroll
                for (int j = 0; j < 8; j++) {
                    const uint32_t nb = (uint32_t)(8 * j + lr) * 32;
                    uint32_t bh[2] = { Kb[nb + c1x], Kb[nb + c2x] };
                    mma_fp16(sacc[j], ahi, bh);
                    mma_fp16(sacc[j], alo, bh);
                }
            }

            // ---- Causal mask (only near diagonal) ----
            const int row0 = q0 + 16 * w + lr;
            if (k0g + 63 > q0 + 16 * w) {
                #pragma unroll
                for (int j = 0; j < 8; j++) {
                    const int c0 = k0g + 8 * j + 2 * lc;
                    if (c0 > row0)         sacc[j][0] = -1e30f;
                    if (c0 + 1 > row0)     sacc[j][1] = -1e30f;
                    if (c0 > row0 + 8)     sacc[j][2] = -1e30f;
                    if (c0 + 1 > row0 + 8) sacc[j][3] = -1e30f;
                }
            }

            // ---- Online softmax ----
            float ml0 = -1e30f, ml1 = -1e30f;
            #pragma unroll
            for (int j = 0; j < 8; j++) {
                ml0 = fmaxf(ml0, fmaxf(sacc[j][0], sacc[j][1]));
                ml1 = fmaxf(ml1, fmaxf(sacc[j][2], sacc[j][3]));
            }
            ml0 = fmaxf(ml0, __shfl_xor_sync(0xffffffffu, ml0, 1));
            ml0 = fmaxf(ml0, __shfl_xor_sync(0xffffffffu, ml0, 2));
            ml1 = fmaxf(ml1, __shfl_xor_sync(0xffffffffu, ml1, 1));
            ml1 = fmaxf(ml1, __shfl_xor_sync(0xffffffffu, ml1, 2));

            const float mn0 = fmaxf(m0, ml0), mn1 = fmaxf(m1, ml1);
            const float fac0 = __expf(m0 - mn0), fac1 = __expf(m1 - mn1);
            float ls0 = 0.0f, ls1 = 0.0f;
            #pragma unroll
            for (int j = 0; j < 8; j++) {
                float p0 = __expf(sacc[j][0] - mn0);
                float p1 = __expf(sacc[j][1] - mn0);
                float p2 = __expf(sacc[j][2] - mn1);
                float p3 = __expf(sacc[j][3] - mn1);
                sacc[j][0] = p0; sacc[j][1] = p1; sacc[j][2] = p2; sacc[j][3] = p3;
                ls0 += p0 + p1; ls1 += p2 + p3;
            }
            ls0 += __shfl_xor_sync(0xffffffffu, ls0, 1);
            ls0 += __shfl_xor_sync(0xffffffffu, ls0, 2);
            ls1 += __shfl_xor_sync(0xffffffffu, ls1, 1);
            ls1 += __shfl_xor_sync(0xffffffffu, ls1, 2);
            l0 = l0 * fac0 + ls0;
            l1 = l1 * fac1 + ls1;
            m0 = mn0; m1 = mn1;

            #pragma unroll
            for (int j = 0; j < 8; j++) {
                oacc[j][0] *= fac0; oacc[j][1] *= fac0;
                oacc[j][2] *= fac1; oacc[j][3] *= fac1;
            }

            // ---- O += P V (P split-2 fp16, V single: 2 mma) ----
            #pragma unroll
            for (int ks = 0; ks < 4; ks++) {
                uint32_t phi[4], plo[4];
                split_h2(sacc[2 * ks][0],     sacc[2 * ks][1],     phi[0], plo[0]);
                split_h2(sacc[2 * ks][2],     sacc[2 * ks][3],     phi[1], plo[1]);
                split_h2(sacc[2 * ks + 1][0], sacc[2 * ks + 1][1], phi[2], plo[2]);
                split_h2(sacc[2 * ks + 1][2], sacc[2 * ks + 1][3], phi[3], plo[3]);
                const uint32_t c1x = ((uint32_t)(8 * ks + lc)) ^ xmask;
                const uint32_t c2x = ((uint32_t)(8 * ks + lc + 4)) ^ xmask;
                #pragma unroll
                for (int j = 0; j < 8; j++) {
                    const uint32_t nb = (uint32_t)(8 * j + lr) * 32;
                    uint32_t bv[2] = { Vb[nb + c1x], Vb[nb + c2x] };
                    mma_fp16(oacc[j], phi, bv);
                    mma_fp16(oacc[j], plo, bv);
                }
            }
        }
        __syncthreads();   // consumers done; buffer free for reuse
    }

    // ---- Write O, normalized ----
    const float inv0 = 1.0f / l0, inv1 = 1.0f / l1;
    const int row = q0 + 16 * w + lr;
    float* ob0 = out + ((size_t)(b * SEQ + row)) * HIDDEN + h * HS;
    float* ob1 = out + ((size_t)(b * SEQ + row + 8)) * HIDDEN + h * HS;
    #pragma unroll
    for (int j = 0; j < 8; j++) {
        const int c = 8 * j + 2 * lc;
        *(float2*)(ob0 + c) = make_float2(oacc[j][0] * inv0, oacc[j][1] * inv0);
        *(float2*)(ob1 + c) = make_float2(oacc[j][2] * inv1, oacc[j][3] * inv1);
    }
}

// ---------------------------------------------------------------------------
// Launch
// ---------------------------------------------------------------------------
extern "C" void kernel_launch(void* const* d_in, const int* in_sizes, int n_in,
                              void* d_out, int out_size) {
    const float* x    = (const float*)d_in[0];
    const float* W    = (const float*)d_in[1];
    const float* bias = (const float*)d_in[2];
    float* out = (float*)d_out;

    cvt_half<<<(unsigned)((NX4 + NW4 + 255) / 256), 256>>>(x, W);

    cudaFuncSetAttribute(qkv_gemm_tc,
                         cudaFuncAttributeMaxDynamicSharedMemorySize,
                         GEMM_SMEM_BYTES);
    qkv_gemm_tc<<<dim3(N_COLS / 128, M_ROWS / 128), 256, GEMM_SMEM_BYTES>>>(bias);

    cudaFuncSetAttribute(attn_mma,
                         cudaFuncAttributeMaxDynamicSharedMemorySize,
                         ATT_SMEM_BYTES);
    attn_mma<<<dim3(SEQ / 128, N_HEADS, BATCH), 256, ATT_SMEM_BYTES>>>(out);
}

// round 15
// speedup vs baseline: 2.0802x; 1.2547x over previous
#include <cuda_runtime.h>
#include <cuda_bf16.h>
#include <cuda_fp16.h>
#include <cstdint>
#include <math.h>

#define N_HEADS 16
#define HIDDEN  1024
#define HS      64
#define BATCH   2
#define SEQ     2048
#define M_ROWS  (BATCH * SEQ)      // 4096
#define N_COLS  (3 * HIDDEN)       // 3072

// fp16 copies of the GEMM inputs (prepass output)
__device__ __half g_xh[(size_t)M_ROWS * HIDDEN];
__device__ __half g_wh[(size_t)HIDDEN * N_COLS];
// Attention operands written by the GEMM epilogue (per (b*16+h) head):
//   Q: pre-scaled x0.125, single fp16, [t][d]
//   K: single fp16, [t][d]
//   V: single fp16, [d][t]
#define HEADELEMS ((size_t)SEQ * HS)
__device__ __half g_qh[(size_t)BATCH * N_HEADS * HEADELEMS];
__device__ __half g_kh[(size_t)BATCH * N_HEADS * HEADELEMS];
__device__ __half g_vh[(size_t)BATCH * N_HEADS * HEADELEMS];

// ---------------------------------------------------------------------------
// Helpers
// ---------------------------------------------------------------------------
__device__ __forceinline__ uint32_t smem_u32(const void* p) {
    uint32_t a;
    asm("{ .reg .u64 t; cvta.to.shared.u64 t, %1; cvt.u32.u64 %0, t; }"
        : "=r"(a) : "l"(p));
    return a;
}
__device__ __forceinline__ void mma_fp16(float* d, const uint32_t* a,
                                         const uint32_t* b) {
    asm volatile(
        "mma.sync.aligned.m16n8k16.row.col.f32.f16.f16.f32 "
        "{%0,%1,%2,%3}, {%4,%5,%6,%7}, {%8,%9}, {%0,%1,%2,%3};"
        : "+f"(d[0]), "+f"(d[1]), "+f"(d[2]), "+f"(d[3])
        : "r"(a[0]), "r"(a[1]), "r"(a[2]), "r"(a[3]),
          "r"(b[0]), "r"(b[1]));
}
__device__ __forceinline__ void ldsm_x4(uint32_t& r0, uint32_t& r1,
                                        uint32_t& r2, uint32_t& r3,
                                        uint32_t addr) {
    asm volatile("ldmatrix.sync.aligned.m8n8.x4.shared.b16 {%0,%1,%2,%3}, [%4];"
                 : "=r"(r0), "=r"(r1), "=r"(r2), "=r"(r3) : "r"(addr));
}
__device__ __forceinline__ void ldsm_x4_t(uint32_t& r0, uint32_t& r1,
                                          uint32_t& r2, uint32_t& r3,
                                          uint32_t addr) {
    asm volatile("ldmatrix.sync.aligned.m8n8.x4.trans.shared.b16 {%0,%1,%2,%3}, [%4];"
                 : "=r"(r0), "=r"(r1), "=r"(r2), "=r"(r3) : "r"(addr));
}
__device__ __forceinline__ uint32_t pack_h2(float x, float y) {
    __half2 h = __floats2half2_rn(x, y);
    return *reinterpret_cast<uint32_t*>(&h);
}
__device__ __forceinline__ void cp16(uint32_t dst, const void* src) {
    asm volatile("cp.async.cg.shared.global [%0], [%1], 16;"
                 :: "r"(dst), "l"(src) : "memory");
}
#define CP_COMMIT() asm volatile("cp.async.commit_group;" ::: "memory")
#define CP_WAIT1()  asm volatile("cp.async.wait_group 1;" ::: "memory")
#define CP_WAIT0()  asm volatile("cp.async.wait_group 0;" ::: "memory")

// ---------------------------------------------------------------------------
// Kernel 0: fp32 -> fp16 prepass for x and W.
// ---------------------------------------------------------------------------
#define NX4 ((size_t)M_ROWS * HIDDEN / 4)   // 1048576
#define NW4 ((size_t)HIDDEN * N_COLS / 4)   // 786432

__global__ void __launch_bounds__(256) cvt_half(const float* __restrict__ x,
                                                const float* __restrict__ W) {
    size_t i = (size_t)blockIdx.x * 256 + threadIdx.x;
    if (i < NX4) {
        float4 v = ((const float4*)x)[i];
        __half2* dst = (__half2*)(g_xh + i * 4);
        dst[0] = __floats2half2_rn(v.x, v.y);
        dst[1] = __floats2half2_rn(v.z, v.w);
    } else if (i < NX4 + NW4) {
        size_t j = i - NX4;
        float4 v = ((const float4*)W)[j];
        __half2* dst = (__half2*)(g_wh + j * 4);
        dst[0] = __floats2half2_rn(v.x, v.y);
        dst[1] = __floats2half2_rn(v.z, v.w);
    }
}

// ---------------------------------------------------------------------------
// Kernel 1: QKV GEMM via mma.sync fp16 m16n8k16 with ldmatrix fragments
// (R12-R14 structure, ~110us, at the measured HMMA floor).
// Epilogue: bias + reshape scatter:
//   Q third: scaled x0.125, single fp16 -> g_qh [t][d]
//   K third: single fp16 -> g_kh [t][d]
//   V third: single fp16 -> g_vh [d][t]
// Reshape algebra: g = 3r + c/1024; e = c%1024; u=g>>11; t=g&2047;
// h=e&15; d=e>>4.
// ---------------------------------------------------------------------------
#define GBK   32
#define GNIT  (HIDDEN / GBK)          // 32
#define CSTR  132
#define AST_B 10240                   // A stage bytes (128 * 80)
#define STG_B 18432                   // A (10240) + B (8192)
#define GEMM_SMEM_BYTES (CSTR * 128 * 4)   // 67584 >= 2*18432

__global__ void __launch_bounds__(256, 2) qkv_gemm_tc(const float* __restrict__ bias)
{
    extern __shared__ char smc[];
    const uint32_t sbase = smem_u32(smc);
    const int tid  = threadIdx.x;
    const int lane = tid & 31;
    const int wid  = tid >> 5;
    const int wm   = wid & 1;
    const int wn   = wid >> 1;
    const int m0 = blockIdx.y * 128, n0 = blockIdx.x * 128;
    const int lr = lane >> 2, lc = lane & 3;

    uint32_t a_dst[2], b_dst[2];
    const __half* a_src[2];
    const __half* b_src[2];
    #pragma unroll
    for (int i = 0; i < 2; i++) {
        int id = tid + i * 256;
        int am = id >> 2, ac = id & 3;
        a_dst[i] = (uint32_t)(am * 80 + ac * 16);
        a_src[i] = g_xh + (size_t)(m0 + am) * HIDDEN + ac * 8;
        int bk = id >> 4, bc = id & 15;
        b_dst[i] = (uint32_t)(AST_B + bk * 256 + ((bc * 16) ^ ((bk & 7) << 4)));
        b_src[i] = g_wh + (size_t)bk * N_COLS + n0 + bc * 8;
    }

    const int g = lane >> 3, r = lane & 7;
    const uint32_t a_lane = (uint32_t)((wm * 64 + ((g & 1) << 3) + r) * 80
                                       + (((g >> 1) << 3) << 1));
    const uint32_t b_rowb  = (uint32_t)((((g & 1) << 3) + r) * 256);
    const uint32_t b_colh0 = (uint32_t)(wn * 32 + ((g >> 1) << 3));
    const uint32_t b_xor   = (uint32_t)(r << 4);

    float acc[4][4][4] = {};

    #pragma unroll
    for (int i = 0; i < 2; i++) {
        cp16(sbase + a_dst[i], a_src[i]);
        cp16(sbase + b_dst[i], b_src[i]);
    }
    CP_COMMIT();

    for (int it = 0; it < GNIT; ++it) {
        const uint32_t buf = (uint32_t)(it & 1) * STG_B;
        if (it + 1 < GNIT) {
            const uint32_t nb = (uint32_t)((it + 1) & 1) * STG_B;
            #pragma unroll
            for (int i = 0; i < 2; i++) {
                cp16(sbase + nb + a_dst[i], a_src[i] + (it + 1) * GBK);
                cp16(sbase + nb + b_dst[i], b_src[i] + (size_t)(it + 1) * GBK * N_COLS);
            }
            CP_COMMIT();
            CP_WAIT1();
        } else {
            CP_WAIT0();
        }
        __syncthreads();

        #pragma unroll
        for (int ks = 0; ks < 2; ks++) {
            uint32_t bf[4][2];
            #pragma unroll
            for (int nblk = 0; nblk < 2; nblk++) {
                uint32_t baddr = sbase + buf + AST_B + b_rowb + (uint32_t)(ks * 4096)
                               + ((((b_colh0 + nblk * 16) << 1)) ^ b_xor);
                uint32_t r0, r1, r2, r3;
                ldsm_x4_t(r0, r1, r2, r3, baddr);
                bf[nblk * 2 + 0][0] = r0; bf[nblk * 2 + 0][1] = r1;
                bf[nblk * 2 + 1][0] = r2; bf[nblk * 2 + 1][1] = r3;
            }
            #pragma unroll
            for (int mf = 0; mf < 4; mf++) {
                uint32_t af[4];
                ldsm_x4(af[0], af[1], af[2], af[3],
                        sbase + buf + a_lane + mf * 1280 + ks * 32);
                #pragma unroll
                for (int nf = 0; nf < 4; nf++)
                    mma_fp16(acc[mf][nf], af, bf[nf]);
            }
        }
        __syncthreads();
    }

    // ---- Epilogue via smem ----
    float* Cs = (float*)smc;
    #pragma unroll
    for (int mf = 0; mf < 4; mf++) {
        const int rr = wm * 64 + mf * 16 + lr;
        #pragma unroll
        for (int nf = 0; nf < 4; nf++) {
            const int c = wn * 32 + nf * 8 + 2 * lc;
            *(float2*)&Cs[rr * CSTR + c]       = make_float2(acc[mf][nf][0], acc[mf][nf][1]);
            *(float2*)&Cs[(rr + 8) * CSTR + c] = make_float2(acc[mf][nf][2], acc[mf][nf][3]);
        }
    }
    __syncthreads();

    {
        const int rr = tid >> 1;
        const int half = tid & 1;
        const int rglob = m0 + rr;
        const int gg = 3 * rglob + (n0 >> 10);
        const int u = gg >> 11, t = gg & 2047;
        const int d0 = (n0 & 1023) >> 4;
        const int kind = u >> 1;            // 0=Q, 1=K, 2=V
        const int bb = u & 1;               // batch
        #pragma unroll
        for (int j = 0; j < 8; j++) {
            const int hh = half * 8 + j;
            float o[8];
            #pragma unroll
            for (int e = 0; e < 8; e++)
                o[e] = Cs[rr * CSTR + hh + 16 * e] + __ldg(&bias[n0 + hh + 16 * e]);
            const size_t head = (size_t)(bb * 16 + hh) * HEADELEMS;
            if (kind == 2) {
                // V: single fp16, [d][t]
                #pragma unroll
                for (int e = 0; e < 8; e++)
                    g_vh[head + (size_t)(d0 + e) * SEQ + t] = __float2half_rn(o[e]);
            } else {
                // Q (scaled) or K: single fp16, [t][d]
                const float sc = (kind == 0) ? 0.125f : 1.0f;
                uint32_t kk[4];
                #pragma unroll
                for (int p = 0; p < 4; p++)
                    kk[p] = pack_h2(o[2 * p] * sc, o[2 * p + 1] * sc);
                __half* dst = (kind == 0) ? g_qh : g_kh;
                *(uint4*)(dst + head + (size_t)t * HS + d0) =
                    make_uint4(kk[0], kk[1], kk[2], kk[3]);
            }
        }
    }
}

// ---------------------------------------------------------------------------
// Kernel 2: flash attention via mma.sync fp16 m16n8k16.
// Q, K, V, P all single fp16: QK = 1 mma, PV = 1 mma -> 64 mma/warp-tile.
// SMEM (u32): Q 0..4095; KV double buffers at 4096 + buf*4096:
//   K +0 (2048), V +2048 (2048). Total 12288 u32 = 48KB.
// ---------------------------------------------------------------------------
#define ATT_SMEM_BYTES (12288 * 4)

__global__ void __launch_bounds__(256, 2) attn_mma(float* __restrict__ out) {
    extern __shared__ uint32_t sm[];
    const uint32_t sb = smem_u32(sm);
    uint32_t* Qs = sm;

    const int tid  = threadIdx.x;
    const int lane = tid & 31;
    const int w    = tid >> 5;          // warp 0..7, rows [16w,16w+16)
    const int lr   = lane >> 2, lc = lane & 3;
    const int qtile = (int)(gridDim.x - 1) - (int)blockIdx.x;  // long CTAs first
    const int h = blockIdx.y, b = blockIdx.z;
    const int q0 = qtile * 128;

    const size_t head = (size_t)(b * 16 + h) * HEADELEMS;
    const __half* qhg = g_qh + head;
    const __half* khg = g_kh + head;
    const __half* vhg = g_vh + head;

    // Per-thread KV chunk mapping (2 chunks of 16B per array per tile)
    uint32_t kv_dst[2];
    int      kv_row[2], kv_c[2];
    #pragma unroll
    for (int i = 0; i < 2; i++) {
        int id = tid + i * 256;
        kv_row[i] = id >> 3;            // 0..63
        kv_c[i]   = id & 7;
        kv_dst[i] = (uint32_t)((kv_row[i] * 32 + ((kv_c[i] ^ (kv_row[i] & 7)) << 2)) * 4);
    }

    // ---- Prologue: Q + KV tile 0 (one group) ----
    #pragma unroll
    for (int i = 0; i < 4; i++) {
        int id = tid + i * 256;
        int rq = id >> 3, cq = id & 7;
        uint32_t d = (uint32_t)((rq * 32 + ((cq ^ (rq & 7)) << 2)) * 4);
        cp16(sb + d, qhg + (size_t)(q0 + rq) * HS + cq * 8);
    }
    #pragma unroll
    for (int i = 0; i < 2; i++) {
        uint32_t base = sb + 4096 * 4;
        cp16(base + kv_dst[i],        khg + (size_t)kv_row[i] * HS + kv_c[i] * 8);
        cp16(base + 8192 + kv_dst[i], vhg + (size_t)kv_row[i] * SEQ + kv_c[i] * 8);
    }
    CP_COMMIT();

    float oacc[8][4];
    #pragma unroll
    for (int j = 0; j < 8; j++)
        #pragma unroll
        for (int k = 0; k < 4; k++) oacc[j][k] = 0.0f;
    float m0 = -1e30f, m1 = -1e30f, l0 = 0.0f, l1 = 0.0f;

    const uint32_t xmask = (uint32_t)lr << 2;

    const int nkt = 2 * qtile + 2;
    for (int kt = 0; kt < nkt; kt++) {
        const int k0g = kt * 64;
        if (kt + 1 < nkt) {
            const int k0n = (kt + 1) * 64;
            const uint32_t base = sb + (4096 + ((kt + 1) & 1) * 4096) * 4;
            #pragma unroll
            for (int i = 0; i < 2; i++) {
                cp16(base + kv_dst[i],        khg + (size_t)(k0n + kv_row[i]) * HS + kv_c[i] * 8);
                cp16(base + 8192 + kv_dst[i], vhg + (size_t)kv_row[i] * SEQ + k0n + kv_c[i] * 8);
            }
            CP_COMMIT();
            CP_WAIT1();
        } else {
            CP_WAIT0();
        }
        __syncthreads();   // tile kt visible to all

        if (k0g <= q0 + 16 * w + 15) {
            const uint32_t* Kb = sm + 4096 + (kt & 1) * 4096;
            const uint32_t* Vb = Kb + 2048;

            // ---- S = Q K^T (single fp16: 1 mma) ----
            float sacc[8][4];
            #pragma unroll
            for (int j = 0; j < 8; j++)
                #pragma unroll
                for (int k = 0; k < 4; k++) sacc[j][k] = 0.0f;

            const int r = 16 * w + lr;
            const uint32_t qbase = r * 32;
            #pragma unroll
            for (int ks = 0; ks < 4; ks++) {
                const uint32_t c1x = ((uint32_t)(8 * ks + lc)) ^ xmask;
                const uint32_t c2x = ((uint32_t)(8 * ks + lc + 4)) ^ xmask;
                uint32_t aq[4];
                aq[0] = Qs[qbase + c1x];
                aq[1] = Qs[qbase + 256 + c1x];
                aq[2] = Qs[qbase + c2x];
                aq[3] = Qs[qbase + 256 + c2x];
                #pragma unroll
                for (int j = 0; j < 8; j++) {
                    const uint32_t nb = (uint32_t)(8 * j + lr) * 32;
                    uint32_t bh[2] = { Kb[nb + c1x], Kb[nb + c2x] };
                    mma_fp16(sacc[j], aq, bh);
                }
            }

            // ---- Causal mask (only near diagonal) ----
            const int row0 = q0 + 16 * w + lr;
            if (k0g + 63 > q0 + 16 * w) {
                #pragma unroll
                for (int j = 0; j < 8; j++) {
                    const int c0 = k0g + 8 * j + 2 * lc;
                    if (c0 > row0)         sacc[j][0] = -1e30f;
                    if (c0 + 1 > row0)     sacc[j][1] = -1e30f;
                    if (c0 > row0 + 8)     sacc[j][2] = -1e30f;
                    if (c0 + 1 > row0 + 8) sacc[j][3] = -1e30f;
                }
            }

            // ---- Online softmax ----
            float ml0 = -1e30f, ml1 = -1e30f;
            #pragma unroll
            for (int j = 0; j < 8; j++) {
                ml0 = fmaxf(ml0, fmaxf(sacc[j][0], sacc[j][1]));
                ml1 = fmaxf(ml1, fmaxf(sacc[j][2], sacc[j][3]));
            }
            ml0 = fmaxf(ml0, __shfl_xor_sync(0xffffffffu, ml0, 1));
            ml0 = fmaxf(ml0, __shfl_xor_sync(0xffffffffu, ml0, 2));
            ml1 = fmaxf(ml1, __shfl_xor_sync(0xffffffffu, ml1, 1));
            ml1 = fmaxf(ml1, __shfl_xor_sync(0xffffffffu, ml1, 2));

            const float mn0 = fmaxf(m0, ml0), mn1 = fmaxf(m1, ml1);
            const float fac0 = __expf(m0 - mn0), fac1 = __expf(m1 - mn1);
            float ls0 = 0.0f, ls1 = 0.0f;
            #pragma unroll
            for (int j = 0; j < 8; j++) {
                float p0 = __expf(sacc[j][0] - mn0);
                float p1 = __expf(sacc[j][1] - mn0);
                float p2 = __expf(sacc[j][2] - mn1);
                float p3 = __expf(sacc[j][3] - mn1);
                sacc[j][0] = p0; sacc[j][1] = p1; sacc[j][2] = p2; sacc[j][3] = p3;
                ls0 += p0 + p1; ls1 += p2 + p3;
            }
            ls0 += __shfl_xor_sync(0xffffffffu, ls0, 1);
            ls0 += __shfl_xor_sync(0xffffffffu, ls0, 2);
            ls1 += __shfl_xor_sync(0xffffffffu, ls1, 1);
            ls1 += __shfl_xor_sync(0xffffffffu, ls1, 2);
            l0 = l0 * fac0 + ls0;
            l1 = l1 * fac1 + ls1;
            m0 = mn0; m1 = mn1;

            #pragma unroll
            for (int j = 0; j < 8; j++) {
                oacc[j][0] *= fac0; oacc[j][1] *= fac0;
                oacc[j][2] *= fac1; oacc[j][3] *= fac1;
            }

            // ---- O += P V (single fp16 P and V: 1 mma) ----
            #pragma unroll
            for (int ks = 0; ks < 4; ks++) {
                uint32_t pf[4];
                pf[0] = pack_h2(sacc[2 * ks][0],     sacc[2 * ks][1]);
                pf[1] = pack_h2(sacc[2 * ks][2],     sacc[2 * ks][3]);
                pf[2] = pack_h2(sacc[2 * ks + 1][0], sacc[2 * ks + 1][1]);
                pf[3] = pack_h2(sacc[2 * ks + 1][2], sacc[2 * ks + 1][3]);
                const uint32_t c1x = ((uint32_t)(8 * ks + lc)) ^ xmask;
                const uint32_t c2x = ((uint32_t)(8 * ks + lc + 4)) ^ xmask;
                #pragma unroll
                for (int j = 0; j < 8; j++) {
                    const uint32_t nb = (uint32_t)(8 * j + lr) * 32;
                    uint32_t bv[2] = { Vb[nb + c1x], Vb[nb + c2x] };
                    mma_fp16(oacc[j], pf, bv);
                }
            }
        }
        __syncthreads();   // consumers done; buffer free for reuse
    }

    // ---- Write O, normalized ----
    const float inv0 = 1.0f / l0, inv1 = 1.0f / l1;
    const int row = q0 + 16 * w + lr;
    float* ob0 = out + ((size_t)(b * SEQ + row)) * HIDDEN + h * HS;
    float* ob1 = out + ((size_t)(b * SEQ + row + 8)) * HIDDEN + h * HS;
    #pragma unroll
    for (int j = 0; j < 8; j++) {
        const int c = 8 * j + 2 * lc;
        *(float2*)(ob0 + c) = make_float2(oacc[j][0] * inv0, oacc[j][1] * inv0);
        *(float2*)(ob1 + c) = make_float2(oacc[j][2] * inv1, oacc[j][3] * inv1);
    }
}

// ---------------------------------------------------------------------------
// Launch
// ---------------------------------------------------------------------------
extern "C" void kernel_launch(void* const* d_in, const int* in_sizes, int n_in,
                              void* d_out, int out_size) {
    const float* x    = (const float*)d_in[0];
    const float* W    = (const float*)d_in[1];
    const float* bias = (const float*)d_in[2];
    float* out = (float*)d_out;

    cvt_half<<<(unsigned)((NX4 + NW4 + 255) / 256), 256>>>(x, W);

    cudaFuncSetAttribute(qkv_gemm_tc,
                         cudaFuncAttributeMaxDynamicSharedMemorySize,
                         GEMM_SMEM_BYTES);
    qkv_gemm_tc<<<dim3(N_COLS / 128, M_ROWS / 128), 256, GEMM_SMEM_BYTES>>>(bias);

    cudaFuncSetAttribute(attn_mma,
                         cudaFuncAttributeMaxDynamicSharedMemorySize,
                         ATT_SMEM_BYTES);
    attn_mma<<<dim3(SEQ / 128, N_HEADS, BATCH), 256, ATT_SMEM_BYTES>>>(out);
}